// round 1
// baseline (speedup 1.0000x reference)
#include <cuda_runtime.h>

typedef unsigned long long ull;

#define BB 64
#define NN 1700
#define CC 256
#define MAXE 16384
#define MTOT (BB*NN)

// ---------------- scratch (device globals; no allocation allowed) ----------------
__device__ float g_h[(size_t)BB*NN*CC];     // GEMM output
__device__ float g_t[(size_t)BB*NN*CC];     // conv output / next input
__device__ int   g_cnt[2*NN];
__device__ int   g_cur[2*NN];
__device__ int   g_ptr[2*(NN+1)];
__device__ float g_dinv[2*NN];
__device__ int   g_esrc[2*MAXE];
__device__ float g_enorm[2*MAXE];

// ---------------- prep kernels ----------------
__global__ void k_init() {
    int i = blockIdx.x*blockDim.x + threadIdx.x;
    if (i < 2*NN) { g_cnt[i] = 0; g_cur[i] = 0; }
}

__global__ void k_count(const int* __restrict__ col, int E, int set) {
    int e = blockIdx.x*blockDim.x + threadIdx.x;
    if (e < E) atomicAdd(&g_cnt[set*NN + col[e]], 1);
}

// single-block scan over NN<=2048 counts + dinv computation
__global__ void k_scan(int set) {
    __shared__ int s[2048];
    int t = threadIdx.x;                   // 1024 threads
    const int* cnt = g_cnt + set*NN;
    for (int i = t; i < 2048; i += 1024) s[i] = (i < NN) ? cnt[i] : 0;
    __syncthreads();
    for (int i = t; i < NN; i += 1024)
        g_dinv[set*NN + i] = rsqrtf((float)(cnt[i] + 1));   // +1 self loop
    for (int off = 1; off < 2048; off <<= 1) {
        int v0 = (t >= off) ? s[t - off] : 0;
        int i1 = t + 1024;
        int v1 = s[i1 - off];
        __syncthreads();
        s[t] += v0; s[i1] += v1;
        __syncthreads();
    }
    int* ptr = g_ptr + set*(NN+1);
    for (int i = t; i <= NN; i += 1024) ptr[i] = (i == 0) ? 0 : s[i-1];
}

__global__ void k_fill(const int* __restrict__ row, const int* __restrict__ col,
                       int E, int set) {
    int e = blockIdx.x*blockDim.x + threadIdx.x;
    if (e >= E) return;
    int r = row[e], c = col[e];
    float nrm = g_dinv[set*NN + r] * g_dinv[set*NN + c];
    int pos = g_ptr[set*(NN+1) + c] + atomicAdd(&g_cur[set*NN + c], 1);
    g_esrc [set*MAXE + pos] = r;
    g_enorm[set*MAXE + pos] = nrm;
}

// ---------------- GEMM: C[M,256] = A[M,256] @ W[256,256], packed f32x2 FMA ----------------
__device__ __forceinline__ ull fma2(ull a, ull b, ull c) {
    ull d;
    asm("fma.rn.f32x2 %0, %1, %2, %3;" : "=l"(d) : "l"(a), "l"(b), "l"(c));
    return d;
}
__device__ __forceinline__ ull dup2(float x) {
    ull d; asm("mov.b64 %0, {%1, %1};" : "=l"(d) : "f"(x)); return d;
}

__global__ __launch_bounds__(256) void k_gemm(const float* __restrict__ A,
                                              const float* __restrict__ W,
                                              float* __restrict__ C) {
    __shared__ __align__(16) float As[8][128];   // transposed A tile
    __shared__ __align__(16) float Bs[8][128];
    int t  = threadIdx.x;
    int m0 = blockIdx.y * 128, n0 = blockIdx.x * 128;
    int tx = t & 15, ty = t >> 4;
    int ar = t >> 1, ac = (t & 1) * 4;          // A-tile load coords
    int br = t >> 5, bc = (t & 31) * 4;         // B-tile load coords

    ull acc[8][4];
    #pragma unroll
    for (int i = 0; i < 8; i++)
        #pragma unroll
        for (int j = 0; j < 4; j++) acc[i][j] = 0ull;

    const float4* Ap = (const float4*)(A + (size_t)(m0 + ar) * CC + ac);
    const float4* Bp = (const float4*)(W + (size_t)br * CC + n0 + bc);

    for (int k0 = 0; k0 < CC; k0 += 8) {
        float4 av = Ap[k0 >> 2];
        float4 bv = Bp[k0 << 6];                // k0 rows * 256 floats / 4
        As[ac+0][ar] = av.x; As[ac+1][ar] = av.y;
        As[ac+2][ar] = av.z; As[ac+3][ar] = av.w;
        *(float4*)&Bs[br][bc] = bv;
        __syncthreads();
        #pragma unroll
        for (int k = 0; k < 8; k++) {
            ull a2[8], b2[4];
            #pragma unroll
            for (int i = 0; i < 8; i++) a2[i] = dup2(As[k][ty*8 + i]);
            #pragma unroll
            for (int j = 0; j < 4; j++) b2[j] = *(const ull*)&Bs[k][tx*8 + j*2];
            #pragma unroll
            for (int i = 0; i < 8; i++)
                #pragma unroll
                for (int j = 0; j < 4; j++)
                    acc[i][j] = fma2(a2[i], b2[j], acc[i][j]);
        }
        __syncthreads();
    }
    #pragma unroll
    for (int i = 0; i < 8; i++) {
        size_t rb = (size_t)(m0 + ty*8 + i) * CC + n0 + tx*8;
        #pragma unroll
        for (int j = 0; j < 4; j++)
            *(ull*)&C[rb + 2*j] = acc[i][j];
    }
}

// ---------------- aggregation: out[b,n,:] = sum_in-edges norm*h[b,src,:] + dinv^2*h[b,n,:] + bias (+res), relu ----------------
__global__ void k_agg(const float* __restrict__ h, int set,
                      const float* __restrict__ bias,
                      const float* __restrict__ residual,
                      float* __restrict__ out) {
    int n = blockIdx.x, b = blockIdx.y, c = threadIdx.x;   // 256 threads = channels
    __shared__ int   s_src[256];
    __shared__ float s_nrm[256];
    const int* ptr = g_ptr + set*(NN+1);
    int p0 = ptr[n], p1 = ptr[n+1];
    float dn = g_dinv[set*NN + n];
    size_t bbase = (size_t)b * NN;
    size_t base  = (bbase + n) * CC;
    float acc = dn * dn * h[base + c];
    for (int j0 = p0; j0 < p1; j0 += 256) {
        int m = min(256, p1 - j0);
        if (c < m) {
            s_src[c] = g_esrc [set*MAXE + j0 + c];
            s_nrm[c] = g_enorm[set*MAXE + j0 + c];
        }
        __syncthreads();
        int j = 0;
        for (; j + 4 <= m; j += 4) {
            float v0 = h[(bbase + s_src[j  ]) * CC + c];
            float v1 = h[(bbase + s_src[j+1]) * CC + c];
            float v2 = h[(bbase + s_src[j+2]) * CC + c];
            float v3 = h[(bbase + s_src[j+3]) * CC + c];
            acc += s_nrm[j  ] * v0;
            acc += s_nrm[j+1] * v1;
            acc += s_nrm[j+2] * v2;
            acc += s_nrm[j+3] * v3;
        }
        for (; j < m; ++j)
            acc += s_nrm[j] * h[(bbase + s_src[j]) * CC + c];
        __syncthreads();
    }
    acc += bias[c];
    if (residual) acc += residual[base + c];
    acc = fmaxf(acc, 0.f);    // conv1/2: relu(out); conv3: relu(out + residual)
    out[base + c] = acc;
}

// ---------------- launch ----------------
extern "C" void kernel_launch(void* const* d_in, const int* in_sizes, int n_in,
                              void* d_out, int out_size) {
    const float* x  = (const float*)d_in[0];
    const float* W1 = (const float*)d_in[1];
    const float* b1 = (const float*)d_in[2];
    const float* W2 = (const float*)d_in[3];
    const float* b2 = (const float*)d_in[4];
    const float* W3 = (const float*)d_in[5];
    const float* b3 = (const float*)d_in[6];
    const int*   sp = (const int*)d_in[7];   // [2, E_sp]
    const int*   tm = (const int*)d_in[8];   // [2, E_tm]
    int Esp = in_sizes[7] / 2;
    int Etm = in_sizes[8] / 2;
    float* out = (float*)d_out;

    float *h, *tbuf;
    cudaGetSymbolAddress((void**)&h,    g_h);
    cudaGetSymbolAddress((void**)&tbuf, g_t);

    // graph prep (both edge sets)
    k_init <<<(2*NN + 255)/256, 256>>>();
    k_count<<<(Esp + 255)/256, 256>>>(sp + Esp, Esp, 0);
    k_count<<<(Etm + 255)/256, 256>>>(tm + Etm, Etm, 1);
    k_scan <<<1, 1024>>>(0);
    k_scan <<<1, 1024>>>(1);
    k_fill <<<(Esp + 255)/256, 256>>>(sp, sp + Esp, Esp, 0);
    k_fill <<<(Etm + 255)/256, 256>>>(tm, tm + Etm, Etm, 1);

    dim3 gg(CC/128, MTOT/128);   // (2, 850)
    dim3 ga(NN, BB);             // (1700, 64)

    // conv1: relu(agg_sp(x@W1) + b1)
    k_gemm<<<gg, 256>>>(x, W1, h);
    k_agg <<<ga, 256>>>(h, 0, b1, nullptr, tbuf);
    // conv2: relu(agg_tm(t@W2) + b2)
    k_gemm<<<gg, 256>>>(tbuf, W2, h);
    k_agg <<<ga, 256>>>(h, 1, b2, nullptr, tbuf);
    // conv3: relu(agg_sp(t@W3) + b3 + x)
    k_gemm<<<gg, 256>>>(tbuf, W3, h);
    k_agg <<<ga, 256>>>(h, 0, b3, x, out);
}

// round 2
// speedup vs baseline: 1.6536x; 1.6536x over previous
#include <cuda_runtime.h>

typedef unsigned long long ull;

#define BB 64
#define NN 1700
#define CC 256
#define MAXE 16384
#define MTOT (BB*NN)

// ---------------- scratch (device globals; no allocation allowed) ----------------
__device__ float g_h[(size_t)BB*NN*CC];     // GEMM output
__device__ float g_t[(size_t)BB*NN*CC];     // conv output / next input
__device__ int   g_cnt[2*NN];
__device__ int   g_cur[2*NN];
__device__ int   g_ptr[2*(NN+1)];
__device__ float g_dinv[2*NN];
__device__ int   g_esrc[2*MAXE];
__device__ float g_enorm[2*MAXE];

// ---------------- prep kernels ----------------
__global__ void k_init() {
    int i = blockIdx.x*blockDim.x + threadIdx.x;
    if (i < 2*NN) { g_cnt[i] = 0; g_cur[i] = 0; }
}

__global__ void k_count(const int* __restrict__ col, int E, int set) {
    int e = blockIdx.x*blockDim.x + threadIdx.x;
    if (e < E) atomicAdd(&g_cnt[set*NN + col[e]], 1);
}

// single-block scan over NN<=2048 counts + dinv computation
__global__ void k_scan(int set) {
    __shared__ int s[2048];
    int t = threadIdx.x;                   // 1024 threads
    const int* cnt = g_cnt + set*NN;
    for (int i = t; i < 2048; i += 1024) s[i] = (i < NN) ? cnt[i] : 0;
    __syncthreads();
    for (int i = t; i < NN; i += 1024)
        g_dinv[set*NN + i] = rsqrtf((float)(cnt[i] + 1));   // +1 self loop
    for (int off = 1; off < 2048; off <<= 1) {
        int v0 = (t >= off) ? s[t - off] : 0;
        int i1 = t + 1024;
        int v1 = s[i1 - off];
        __syncthreads();
        s[t] += v0; s[i1] += v1;
        __syncthreads();
    }
    int* ptr = g_ptr + set*(NN+1);
    for (int i = t; i <= NN; i += 1024) ptr[i] = (i == 0) ? 0 : s[i-1];
}

__global__ void k_fill(const int* __restrict__ row, const int* __restrict__ col,
                       int E, int set) {
    int e = blockIdx.x*blockDim.x + threadIdx.x;
    if (e >= E) return;
    int r = row[e], c = col[e];
    float nrm = g_dinv[set*NN + r] * g_dinv[set*NN + c];
    int pos = g_ptr[set*(NN+1) + c] + atomicAdd(&g_cur[set*NN + c], 1);
    g_esrc [set*MAXE + pos] = r;
    g_enorm[set*MAXE + pos] = nrm;
}

// ---------------- GEMM: C[M,256] = A[M,256] @ W[256,256], packed f32x2 FMA ----------------
__device__ __forceinline__ ull fma2(ull a, ull b, ull c) {
    ull d;
    asm("fma.rn.f32x2 %0, %1, %2, %3;" : "=l"(d) : "l"(a), "l"(b), "l"(c));
    return d;
}
__device__ __forceinline__ ull dup2(float x) {
    ull d; asm("mov.b64 %0, {%1, %1};" : "=l"(d) : "f"(x)); return d;
}

// 128x128 tile, 256 threads, 8x8 per thread (n packed in f32x2 pairs),
// double-buffered smem, conflict-free B-fragment reads.
__global__ __launch_bounds__(256, 2) void k_gemm(const float* __restrict__ A,
                                                 const float* __restrict__ W,
                                                 float* __restrict__ C) {
    __shared__ __align__(16) float As[2][8][128];   // [stage][k][m]  (transposed A)
    __shared__ __align__(16) float Bs[2][8][128];   // [stage][k][n]
    int t  = threadIdx.x;
    int m0 = blockIdx.y * 128, n0 = blockIdx.x * 128;
    int tx = t & 15, ty = t >> 4;               // n-group / m-group
    int ar = t >> 1, ac = (t & 1) * 4;          // A-tile load coords
    int br = t >> 5, bc = (t & 31) * 4;         // B-tile load coords

    ull acc[8][4];
    #pragma unroll
    for (int i = 0; i < 8; i++)
        #pragma unroll
        for (int j = 0; j < 4; j++) acc[i][j] = 0ull;

    const float4* Ap = (const float4*)(A + (size_t)(m0 + ar) * CC + ac);
    const float4* Bp = (const float4*)(W + (size_t)br * CC + n0 + bc);

    // prologue: stage 0
    {
        float4 av = Ap[0];
        float4 bv = Bp[0];
        As[0][ac+0][ar] = av.x; As[0][ac+1][ar] = av.y;
        As[0][ac+2][ar] = av.z; As[0][ac+3][ar] = av.w;
        *(float4*)&Bs[0][br][bc] = bv;
    }
    __syncthreads();

    int s = 0;
    for (int k0 = 0; k0 < CC; k0 += 8) {
        int kn = k0 + 8;
        float4 av, bv;
        if (kn < CC) {                 // prefetch next stage into registers
            av = Ap[kn >> 2];
            bv = Bp[kn << 6];          // kn rows * 256 floats / 4
        }
        #pragma unroll
        for (int k = 0; k < 8; k++) {
            ull a2[8], b2[4];
            #pragma unroll
            for (int i = 0; i < 8; i++) a2[i] = dup2(As[s][k][ty*8 + i]);
            #pragma unroll
            for (int j = 0; j < 4; j++)
                b2[j] = *(const ull*)&Bs[s][k][(tx + j*16) * 2];
            #pragma unroll
            for (int i = 0; i < 8; i++)
                #pragma unroll
                for (int j = 0; j < 4; j++)
                    acc[i][j] = fma2(a2[i], b2[j], acc[i][j]);
        }
        if (kn < CC) {
            int ns = s ^ 1;
            As[ns][ac+0][ar] = av.x; As[ns][ac+1][ar] = av.y;
            As[ns][ac+2][ar] = av.z; As[ns][ac+3][ar] = av.w;
            *(float4*)&Bs[ns][br][bc] = bv;
            __syncthreads();
            s = ns;
        }
    }
    #pragma unroll
    for (int i = 0; i < 8; i++) {
        size_t rb = (size_t)(m0 + ty*8 + i) * CC + n0;
        #pragma unroll
        for (int j = 0; j < 4; j++)
            *(ull*)&C[rb + tx*2 + j*32] = acc[i][j];
    }
}

// ---------------- aggregation ----------------
// out[b,n,:] = relu( sum_in-edges norm*h[b,src,:] + dinv^2*h[b,n,:] + bias (+res) )
// 64-thread groups (float4 channels), 4 nodes per 256-thread block.
__global__ __launch_bounds__(256) void k_agg(const float* __restrict__ h, int set,
                                             const float* __restrict__ bias,
                                             const float* __restrict__ residual,
                                             float* __restrict__ out) {
    int g    = threadIdx.x >> 6;           // node sub-group 0..3
    int lane = threadIdx.x & 63;           // channel/4
    int n = blockIdx.x * 4 + g;
    int b = blockIdx.y;
    if (n >= NN) return;

    const int* ptr = g_ptr + set*(NN+1);
    int p0 = __ldg(&ptr[n]), p1 = __ldg(&ptr[n+1]);
    float dn = __ldg(&g_dinv[set*NN + n]);
    size_t bbase = (size_t)b * NN;
    size_t base  = (bbase + n) * CC + lane*4;

    float4 sv = *(const float4*)&h[base];
    float w = dn * dn;
    float4 acc;
    acc.x = w*sv.x; acc.y = w*sv.y; acc.z = w*sv.z; acc.w = w*sv.w;

    int off = set*MAXE;
    int j = p0;
    for (; j + 2 <= p1; j += 2) {
        int   s0 = __ldg(&g_esrc [off + j]);
        int   s1 = __ldg(&g_esrc [off + j + 1]);
        float w0 = __ldg(&g_enorm[off + j]);
        float w1 = __ldg(&g_enorm[off + j + 1]);
        float4 v0 = *(const float4*)&h[(bbase + s0)*CC + lane*4];
        float4 v1 = *(const float4*)&h[(bbase + s1)*CC + lane*4];
        acc.x += w0*v0.x + w1*v1.x;
        acc.y += w0*v0.y + w1*v1.y;
        acc.z += w0*v0.z + w1*v1.z;
        acc.w += w0*v0.w + w1*v1.w;
    }
    if (j < p1) {
        int   s0 = __ldg(&g_esrc [off + j]);
        float w0 = __ldg(&g_enorm[off + j]);
        float4 v0 = *(const float4*)&h[(bbase + s0)*CC + lane*4];
        acc.x += w0*v0.x; acc.y += w0*v0.y; acc.z += w0*v0.z; acc.w += w0*v0.w;
    }

    float4 bi = *(const float4*)&bias[lane*4];
    acc.x += bi.x; acc.y += bi.y; acc.z += bi.z; acc.w += bi.w;
    if (residual) {
        float4 rv = *(const float4*)&residual[base];
        acc.x += rv.x; acc.y += rv.y; acc.z += rv.z; acc.w += rv.w;
    }
    acc.x = fmaxf(acc.x, 0.f); acc.y = fmaxf(acc.y, 0.f);
    acc.z = fmaxf(acc.z, 0.f); acc.w = fmaxf(acc.w, 0.f);
    *(float4*)&out[base] = acc;
}

// ---------------- launch ----------------
extern "C" void kernel_launch(void* const* d_in, const int* in_sizes, int n_in,
                              void* d_out, int out_size) {
    const float* x  = (const float*)d_in[0];
    const float* W1 = (const float*)d_in[1];
    const float* b1 = (const float*)d_in[2];
    const float* W2 = (const float*)d_in[3];
    const float* b2 = (const float*)d_in[4];
    const float* W3 = (const float*)d_in[5];
    const float* b3 = (const float*)d_in[6];
    const int*   sp = (const int*)d_in[7];   // [2, E_sp]
    const int*   tm = (const int*)d_in[8];   // [2, E_tm]
    int Esp = in_sizes[7] / 2;
    int Etm = in_sizes[8] / 2;
    float* out = (float*)d_out;

    float *h, *tbuf;
    cudaGetSymbolAddress((void**)&h,    g_h);
    cudaGetSymbolAddress((void**)&tbuf, g_t);

    dim3 gg(CC/128, MTOT/128);        // (2, 850)
    dim3 ga((NN + 3)/4, BB);          // (425, 64)

    // graph prep: exactly 5 launches so launch #6 (profiled by ncu -s 5 -c 1) is k_gemm
    k_init <<<(2*NN + 255)/256, 256>>>();
    k_count<<<(Esp + 255)/256, 256>>>(sp + Esp, Esp, 0);
    k_count<<<(Etm + 255)/256, 256>>>(tm + Etm, Etm, 1);
    k_scan <<<1, 1024>>>(0);
    k_scan <<<1, 1024>>>(1);

    // conv1 GEMM (launch #6 — profiled)
    k_gemm<<<gg, 256>>>(x, W1, h);

    // CSR fill (independent of GEMM; needed before first agg)
    k_fill <<<(Esp + 255)/256, 256>>>(sp, sp + Esp, Esp, 0);
    k_fill <<<(Etm + 255)/256, 256>>>(tm, tm + Etm, Etm, 1);

    // conv1: relu(agg_sp(x@W1) + b1)
    k_agg <<<ga, 256>>>(h, 0, b1, nullptr, tbuf);
    // conv2: relu(agg_tm(t@W2) + b2)
    k_gemm<<<gg, 256>>>(tbuf, W2, h);
    k_agg <<<ga, 256>>>(h, 1, b2, nullptr, tbuf);
    // conv3: relu(agg_sp(t@W3) + b3 + x)
    k_gemm<<<gg, 256>>>(tbuf, W3, h);
    k_agg <<<ga, 256>>>(h, 0, b3, x, out);
}

// round 4
// speedup vs baseline: 2.4601x; 1.4877x over previous
#include <cuda_runtime.h>
#include <cuda_bf16.h>
#include <cstdint>

typedef unsigned long long ull;

#define BB 64
#define NN 1700
#define CC 256
#define MAXE 16384
#define MTOT (BB*NN)
#define MTILES (MTOT/128)          // 850

// ---------------- scratch (device globals; no allocation allowed) ----------------
__device__ float g_h[(size_t)BB*NN*CC];                    // GEMM output (fp32)
__device__ __nv_bfloat16 g_ah[(size_t)MTOT*CC];            // A hi image (chunked+swizzled)
__device__ __nv_bfloat16 g_al[(size_t)MTOT*CC];            // A lo image
__device__ __nv_bfloat16 g_bh[3*65536];                    // B hi images per layer
__device__ __nv_bfloat16 g_bl[3*65536];                    // B lo images per layer
__device__ int   g_cnt[2*NN];
__device__ int   g_cur[2*NN];
__device__ int   g_ptr[2*(NN+1)];
__device__ float g_dinv[2*NN];
__device__ int   g_esrc[2*MAXE];
__device__ float g_enorm[2*MAXE];

// ---------------- PTX helpers (all sm_80-class: valid for compute_103) ----------------
__device__ __forceinline__ uint32_t smem_u32(const void* p) {
    uint32_t a;
    asm("{ .reg .u64 t; cvta.to.shared.u64 t, %1; cvt.u32.u64 %0, t; }" : "=r"(a) : "l"(p));
    return a;
}
#define LDSM4(r0,r1,r2,r3,addr) \
    asm volatile("ldmatrix.sync.aligned.m8n8.x4.shared.b16 {%0,%1,%2,%3}, [%4];" \
        : "=r"(r0),"=r"(r1),"=r"(r2),"=r"(r3) : "r"(addr))
#define MMA16816(d, a, b0, b1) \
    asm volatile("mma.sync.aligned.m16n8k16.row.col.f32.bf16.bf16.f32 " \
        "{%0,%1,%2,%3},{%4,%5,%6,%7},{%8,%9},{%0,%1,%2,%3};" \
        : "+f"((d)[0]),"+f"((d)[1]),"+f"((d)[2]),"+f"((d)[3]) \
        : "r"((a)[0]),"r"((a)[1]),"r"((a)[2]),"r"((a)[3]), "r"(b0),"r"(b1))
#define CPASYNC16(dst, src) \
    asm volatile("cp.async.cg.shared.global [%0], [%1], 16;" :: "r"(dst), "l"(src))
#define CPCOMMIT() asm volatile("cp.async.commit_group;")
#define CPWAIT(n)  asm volatile("cp.async.wait_group %0;" :: "n"(n))

// chunked image element offset within a 128x32 block, 16B-chunk XOR swizzle:
// row r (0..127, 64B/row), kin (0..31): kc' = (kin>>3) ^ ((r>>1)&3)
__device__ __forceinline__ uint32_t swz_elem(int r, int kin) {
    return (uint32_t)(r*32 + ((((kin>>3) ^ ((r>>1)&3)))<<3) + (kin&7));
}

// ---------------- prep kernels ----------------
__global__ void k_init() {
    int i = blockIdx.x*blockDim.x + threadIdx.x;
    if (i < 2*NN) { g_cnt[i] = 0; g_cur[i] = 0; }
}
__global__ void k_count(const int* __restrict__ col, int E, int set) {
    int e = blockIdx.x*blockDim.x + threadIdx.x;
    if (e < E) atomicAdd(&g_cnt[set*NN + col[e]], 1);
}
__global__ void k_scan(int set) {
    __shared__ int s[2048];
    int t = threadIdx.x;
    const int* cnt = g_cnt + set*NN;
    for (int i = t; i < 2048; i += 1024) s[i] = (i < NN) ? cnt[i] : 0;
    __syncthreads();
    for (int i = t; i < NN; i += 1024)
        g_dinv[set*NN + i] = rsqrtf((float)(cnt[i] + 1));
    for (int off = 1; off < 2048; off <<= 1) {
        int v0 = (t >= off) ? s[t - off] : 0;
        int i1 = t + 1024;
        int v1 = s[i1 - off];
        __syncthreads();
        s[t] += v0; s[i1] += v1;
        __syncthreads();
    }
    int* ptr = g_ptr + set*(NN+1);
    for (int i = t; i <= NN; i += 1024) ptr[i] = (i == 0) ? 0 : s[i-1];
}
__global__ void k_fill(const int* __restrict__ row, const int* __restrict__ col, int E, int set) {
    int e = blockIdx.x*blockDim.x + threadIdx.x;
    if (e >= E) return;
    int r = row[e], c = col[e];
    float nrm = g_dinv[set*NN + r] * g_dinv[set*NN + c];
    int pos = g_ptr[set*(NN+1) + c] + atomicAdd(&g_cur[set*NN + c], 1);
    g_esrc [set*MAXE + pos] = r;
    g_enorm[set*MAXE + pos] = nrm;
}

// ---------------- bf16 hi/lo split ----------------
__device__ __forceinline__ void split4(float4 v, uint2& hi, uint2& lo) {
    __nv_bfloat16 h0 = __float2bfloat16(v.x), h1 = __float2bfloat16(v.y),
                  h2 = __float2bfloat16(v.z), h3 = __float2bfloat16(v.w);
    __nv_bfloat16 l0 = __float2bfloat16(v.x - __bfloat162float(h0));
    __nv_bfloat16 l1 = __float2bfloat16(v.y - __bfloat162float(h1));
    __nv_bfloat16 l2 = __float2bfloat16(v.z - __bfloat162float(h2));
    __nv_bfloat16 l3 = __float2bfloat16(v.w - __bfloat162float(h3));
    __nv_bfloat162 hA = __nv_bfloat162(h0, h1), hB = __nv_bfloat162(h2, h3);
    __nv_bfloat162 lA = __nv_bfloat162(l0, l1), lB = __nv_bfloat162(l2, l3);
    hi.x = *(uint32_t*)&hA; hi.y = *(uint32_t*)&hB;
    lo.x = *(uint32_t*)&lA; lo.y = *(uint32_t*)&lB;
}

// x fp32 [M,256] -> hi/lo images: [tile][chunk(8)][128x32 swizzled]
__global__ __launch_bounds__(256) void k_convA(const float* __restrict__ X) {
    int idx = blockIdx.x * 256 + threadIdx.x;
    int m = idx >> 6, lane = idx & 63;
    if (m >= MTOT) return;
    int k = lane * 4;
    float4 v = *(const float4*)&X[(size_t)m * CC + k];
    uint2 hi, lo; split4(v, hi, lo);
    int tile = m >> 7, mi = m & 127, chunk = k >> 5, kin = k & 31;
    size_t eo = (size_t)(tile*8 + chunk)*4096 + swz_elem(mi, kin);
    *(uint2*)(g_ah + eo) = hi;
    *(uint2*)(g_al + eo) = lo;
}

// W fp32 [k=256][n=256] -> hi/lo images: [nhalf(2)][chunk(8)][128x32 swizzled] (row=n, col=k)
__global__ __launch_bounds__(256) void k_convW(const float* __restrict__ W, int layer) {
    int idx = blockIdx.x * 256 + threadIdx.x;     // 64 blocks x 256
    int n = idx >> 6, kq = idx & 63;
    if (n >= 256) return;
    int k = kq * 4;
    float4 v = make_float4(W[(size_t)(k+0)*CC + n], W[(size_t)(k+1)*CC + n],
                           W[(size_t)(k+2)*CC + n], W[(size_t)(k+3)*CC + n]);
    uint2 hi, lo; split4(v, hi, lo);
    int nh = n >> 7, ni = n & 127, chunk = k >> 5, kin = k & 31;
    size_t eo = (size_t)layer*65536 + (size_t)(nh*8 + chunk)*4096 + swz_elem(ni, kin);
    *(uint2*)(g_bh + eo) = hi;
    *(uint2*)(g_bl + eo) = lo;
}

// ---------------- HMMA GEMM: H = A @ W via bf16 3-product split ----------------
// grid (2, 850): blockIdx.x = n-half, blockIdx.y = m-tile. 256 thr, 128x128 tile.
// dyn smem: 2 stages x 32KB {Ahi, Alo, Bhi, Blo each 8KB}
#define GSM 65536
__global__ __launch_bounds__(256) void k_gemm_mma(const __nv_bfloat16* __restrict__ Bh,
                                                  const __nv_bfloat16* __restrict__ Bl,
                                                  float* __restrict__ H) {
    extern __shared__ __align__(128) char smc[];
    uint32_t sb = smem_u32(smc);
    int tid = threadIdx.x, wid = tid >> 5, lane = tid & 31;
    int nh = blockIdx.x, tile = blockIdx.y;
    int mwarp = (wid >> 1) * 32, nwarp = (wid & 1) * 64;

    const char* gAh = (const char*)(g_ah + (size_t)tile * 8 * 4096);
    const char* gAl = (const char*)(g_al + (size_t)tile * 8 * 4096);
    const char* gBh = (const char*)(Bh + (size_t)nh * 8 * 4096);
    const char* gBl = (const char*)(Bl + (size_t)nh * 8 * 4096);

    // ldmatrix address precompute
    int r15 = lane & 15, hi2 = lane >> 4;
    uint32_t aoff[2]; int asw[2];
    #pragma unroll
    for (int i = 0; i < 2; i++) {
        int mr = mwarp + i*16 + r15;
        aoff[i] = mr * 64; asw[i] = (mr >> 1) & 3;
    }
    uint32_t boff[4]; int bsw[4];
    #pragma unroll
    for (int j = 0; j < 4; j++) {
        int nr = nwarp + j*16 + r15;
        boff[j] = nr * 64; bsw[j] = (nr >> 1) & 3;
    }

    float d[2][8][4];
    #pragma unroll
    for (int i = 0; i < 2; i++)
        #pragma unroll
        for (int j = 0; j < 8; j++)
            #pragma unroll
            for (int q = 0; q < 4; q++) d[i][j][q] = 0.f;

    // stage copy: 4 sub-buffers x 8KB; 2 x 16B per thread per sub-buffer
    #define ISSUE(c, st) do { \
        size_t go = (size_t)(c) * 8192; \
        uint32_t so = sb + (st) * 32768; \
        _Pragma("unroll") \
        for (int q = 0; q < 2; q++) { \
            uint32_t off = (uint32_t)(tid + q*256) * 16; \
            CPASYNC16(so +         off, gAh + go + off); \
            CPASYNC16(so +  8192 + off, gAl + go + off); \
            CPASYNC16(so + 16384 + off, gBh + go + off); \
            CPASYNC16(so + 24576 + off, gBl + go + off); \
        } \
        CPCOMMIT(); \
    } while (0)

    ISSUE(0, 0);
    for (int c = 0; c < 8; c++) {
        int st = c & 1;
        if (c < 7) { ISSUE(c+1, st^1); CPWAIT(1); }
        else       { CPWAIT(0); }
        __syncthreads();
        uint32_t base = sb + st * 32768;
        #pragma unroll
        for (int s = 0; s < 2; s++) {
            uint32_t ah[2][4], al[2][4];
            #pragma unroll
            for (int i = 0; i < 2; i++) {
                uint32_t kc = (uint32_t)((((s<<1)|hi2) ^ asw[i]) << 4);
                LDSM4(ah[i][0],ah[i][1],ah[i][2],ah[i][3], base + aoff[i] + kc);
                LDSM4(al[i][0],al[i][1],al[i][2],al[i][3], base + 8192 + aoff[i] + kc);
            }
            #pragma unroll
            for (int j = 0; j < 4; j++) {
                uint32_t kc = (uint32_t)((((s<<1)|hi2) ^ bsw[j]) << 4);
                uint32_t bh0,bh1,bh2,bh3, bl0,bl1,bl2,bl3;
                LDSM4(bh0,bh1,bh2,bh3, base + 16384 + boff[j] + kc);
                LDSM4(bl0,bl1,bl2,bl3, base + 24576 + boff[j] + kc);
                #pragma unroll
                for (int i = 0; i < 2; i++) {
                    MMA16816(d[i][2*j],   ah[i], bh0, bh2);
                    MMA16816(d[i][2*j+1], ah[i], bh1, bh3);
                    MMA16816(d[i][2*j],   ah[i], bl0, bl2);
                    MMA16816(d[i][2*j+1], ah[i], bl1, bl3);
                    MMA16816(d[i][2*j],   al[i], bh0, bh2);
                    MMA16816(d[i][2*j+1], al[i], bh1, bh3);
                }
            }
        }
        __syncthreads();
    }

    // epilogue: fp32 store
    int rr = lane >> 2, cp = (lane & 3) * 2;
    #pragma unroll
    for (int i = 0; i < 2; i++) {
        size_t row = (size_t)tile*128 + mwarp + i*16 + rr;
        #pragma unroll
        for (int j = 0; j < 8; j++) {
            int col = nh*128 + nwarp + j*8 + cp;
            float2 v0 = make_float2(d[i][j][0], d[i][j][1]);
            float2 v1 = make_float2(d[i][j][2], d[i][j][3]);
            *(float2*)&H[row*CC + col]     = v0;
            *(float2*)&H[(row+8)*CC + col] = v1;
        }
    }
}

// ---------------- aggregation ----------------
// acc = sum_in-edges norm*h[b,src,:] + dinv^2*h[b,n,:] + bias (+res), relu.
// write_img: write hi/lo A images (next GEMM input); else fp32 out.
__global__ __launch_bounds__(256) void k_agg(const float* __restrict__ h, int set,
                                             const float* __restrict__ bias,
                                             const float* __restrict__ residual,
                                             float* __restrict__ out, int write_img) {
    int g    = threadIdx.x >> 6;
    int lane = threadIdx.x & 63;
    int n = blockIdx.x * 4 + g;
    int b = blockIdx.y;
    if (n >= NN) return;

    const int* ptr = g_ptr + set*(NN+1);
    int p0 = __ldg(&ptr[n]), p1 = __ldg(&ptr[n+1]);
    float dn = __ldg(&g_dinv[set*NN + n]);
    size_t bbase = (size_t)b * NN;
    size_t base  = (bbase + n) * CC + lane*4;

    float4 sv = *(const float4*)&h[base];
    float w = dn * dn;
    float4 acc;
    acc.x = w*sv.x; acc.y = w*sv.y; acc.z = w*sv.z; acc.w = w*sv.w;

    int off = set*MAXE;
    int j = p0;
    for (; j + 2 <= p1; j += 2) {
        int   s0 = __ldg(&g_esrc [off + j]);
        int   s1 = __ldg(&g_esrc [off + j + 1]);
        float w0 = __ldg(&g_enorm[off + j]);
        float w1 = __ldg(&g_enorm[off + j + 1]);
        float4 v0 = *(const float4*)&h[(bbase + s0)*CC + lane*4];
        float4 v1 = *(const float4*)&h[(bbase + s1)*CC + lane*4];
        acc.x += w0*v0.x + w1*v1.x;
        acc.y += w0*v0.y + w1*v1.y;
        acc.z += w0*v0.z + w1*v1.z;
        acc.w += w0*v0.w + w1*v1.w;
    }
    if (j < p1) {
        int   s0 = __ldg(&g_esrc [off + j]);
        float w0 = __ldg(&g_enorm[off + j]);
        float4 v0 = *(const float4*)&h[(bbase + s0)*CC + lane*4];
        acc.x += w0*v0.x; acc.y += w0*v0.y; acc.z += w0*v0.z; acc.w += w0*v0.w;
    }

    float4 bi = *(const float4*)&bias[lane*4];
    acc.x += bi.x; acc.y += bi.y; acc.z += bi.z; acc.w += bi.w;
    if (residual) {
        float4 rv = *(const float4*)&residual[base];
        acc.x += rv.x; acc.y += rv.y; acc.z += rv.z; acc.w += rv.w;
    }
    acc.x = fmaxf(acc.x, 0.f); acc.y = fmaxf(acc.y, 0.f);
    acc.z = fmaxf(acc.z, 0.f); acc.w = fmaxf(acc.w, 0.f);

    if (write_img) {
        uint2 hi, lo; split4(acc, hi, lo);
        int m = (int)(bbase + n);
        int tile = m >> 7, mi = m & 127, k = lane*4, chunk = k >> 5, kin = k & 31;
        size_t eo = (size_t)(tile*8 + chunk)*4096 + swz_elem(mi, kin);
        *(uint2*)(g_ah + eo) = hi;
        *(uint2*)(g_al + eo) = lo;
    } else {
        *(float4*)&out[base] = acc;
    }
}

// ---------------- launch ----------------
extern "C" void kernel_launch(void* const* d_in, const int* in_sizes, int n_in,
                              void* d_out, int out_size) {
    const float* x  = (const float*)d_in[0];
    const float* W1 = (const float*)d_in[1];
    const float* b1 = (const float*)d_in[2];
    const float* W2 = (const float*)d_in[3];
    const float* b2 = (const float*)d_in[4];
    const float* W3 = (const float*)d_in[5];
    const float* b3 = (const float*)d_in[6];
    const int*   sp = (const int*)d_in[7];
    const int*   tm = (const int*)d_in[8];
    int Esp = in_sizes[7] / 2;
    int Etm = in_sizes[8] / 2;
    float* out = (float*)d_out;

    float* h; __nv_bfloat16 *bh, *bl;
    cudaGetSymbolAddress((void**)&h,  g_h);
    cudaGetSymbolAddress((void**)&bh, g_bh);
    cudaGetSymbolAddress((void**)&bl, g_bl);

    cudaFuncSetAttribute(k_gemm_mma, cudaFuncAttributeMaxDynamicSharedMemorySize, GSM);

    dim3 gg(2, MTILES);               // (2, 850)
    dim3 ga((NN + 3)/4, BB);          // (425, 64)

    // slots 1-4: conversions; slot 5 = GEMM1 (ncu samples slot 5)
    k_convA<<<(MTOT*64 + 255)/256, 256>>>(x);
    k_convW<<<64, 256>>>(W1, 0);
    k_convW<<<64, 256>>>(W2, 1);
    k_convW<<<64, 256>>>(W3, 2);
    k_gemm_mma<<<gg, 256, GSM>>>(bh, bl, h);

    // graph prep
    k_init <<<(2*NN + 255)/256, 256>>>();
    k_count<<<(Esp + 255)/256, 256>>>(sp + Esp, Esp, 0);
    k_count<<<(Etm + 255)/256, 256>>>(tm + Etm, Etm, 1);
    k_scan <<<1, 1024>>>(0);
    k_scan <<<1, 1024>>>(1);
    k_fill <<<(Esp + 255)/256, 256>>>(sp, sp + Esp, Esp, 0);
    k_fill <<<(Etm + 255)/256, 256>>>(tm, tm + Etm, Etm, 1);

    // conv1: relu(agg_sp(x@W1)+b1) -> images
    k_agg<<<ga, 256>>>(h, 0, b1, nullptr, nullptr, 1);
    // conv2: relu(agg_tm(.@W2)+b2) -> images
    k_gemm_mma<<<gg, 256, GSM>>>(bh + 65536, bl + 65536, h);
    k_agg<<<ga, 256>>>(h, 1, b2, nullptr, nullptr, 1);
    // conv3: relu(agg_sp(.@W3)+b3+x) -> out
    k_gemm_mma<<<gg, 256, GSM>>>(bh + 2*65536, bl + 2*65536, h);
    k_agg<<<ga, 256>>>(h, 0, b3, x, out, 0);
}

// round 5
// speedup vs baseline: 2.5739x; 1.0463x over previous
#include <cuda_runtime.h>
#include <cuda_bf16.h>
#include <cstdint>

typedef unsigned long long ull;

#define BB 64
#define NN 1700
#define CC 256
#define MAXE 16384
#define MTOT (BB*NN)
#define MTILES (MTOT/128)          // 850

// ---------------- scratch (device globals; no allocation allowed) ----------------
__device__ float g_h[(size_t)BB*NN*CC];                    // GEMM output (fp32)
__device__ __nv_bfloat16 g_ah[(size_t)MTOT*CC];            // A hi image (chunked+swizzled)
__device__ __nv_bfloat16 g_al[(size_t)MTOT*CC];            // A lo image
__device__ __nv_bfloat16 g_bh[3*65536];                    // B hi images per layer
__device__ __nv_bfloat16 g_bl[3*65536];                    // B lo images per layer
__device__ int   g_cnt[2*NN];
__device__ int   g_cur[2*NN];
__device__ int   g_ptr[2*(NN+1)];
__device__ float g_dinv[2*NN];
__device__ int   g_esrc[2*MAXE];
__device__ float g_enorm[2*MAXE];

// ---------------- PTX helpers (all sm_80-class: valid for compute_103) ----------------
__device__ __forceinline__ uint32_t smem_u32(const void* p) {
    uint32_t a;
    asm("{ .reg .u64 t; cvta.to.shared.u64 t, %1; cvt.u32.u64 %0, t; }" : "=r"(a) : "l"(p));
    return a;
}
#define LDSM4(r0,r1,r2,r3,addr) \
    asm volatile("ldmatrix.sync.aligned.m8n8.x4.shared.b16 {%0,%1,%2,%3}, [%4];" \
        : "=r"(r0),"=r"(r1),"=r"(r2),"=r"(r3) : "r"(addr))
#define MMA16816(d, a, b0, b1) \
    asm volatile("mma.sync.aligned.m16n8k16.row.col.f32.bf16.bf16.f32 " \
        "{%0,%1,%2,%3},{%4,%5,%6,%7},{%8,%9},{%0,%1,%2,%3};" \
        : "+f"((d)[0]),"+f"((d)[1]),"+f"((d)[2]),"+f"((d)[3]) \
        : "r"((a)[0]),"r"((a)[1]),"r"((a)[2]),"r"((a)[3]), "r"(b0),"r"(b1))
#define CPASYNC16(dst, src) \
    asm volatile("cp.async.cg.shared.global [%0], [%1], 16;" :: "r"(dst), "l"(src))
#define CPCOMMIT() asm volatile("cp.async.commit_group;")
#define CPWAIT(n)  asm volatile("cp.async.wait_group %0;" :: "n"(n))

// chunked image element offset within a 128x32 block, 16B-chunk XOR swizzle:
// row r (0..127, 64B/row), kin (0..31): kc' = (kin>>3) ^ ((r>>1)&3)
__device__ __forceinline__ uint32_t swz_elem(int r, int kin) {
    return (uint32_t)(r*32 + ((((kin>>3) ^ ((r>>1)&3)))<<3) + (kin&7));
}

// ---------------- prep kernels ----------------
__global__ void k_init() {
    int i = blockIdx.x*blockDim.x + threadIdx.x;
    if (i < 2*NN) { g_cnt[i] = 0; g_cur[i] = 0; }
}
__global__ void k_count(const int* __restrict__ col, int E, int set) {
    int e = blockIdx.x*blockDim.x + threadIdx.x;
    if (e < E) atomicAdd(&g_cnt[set*NN + col[e]], 1);
}
__global__ void k_scan(int set) {
    __shared__ int s[2048];
    int t = threadIdx.x;
    const int* cnt = g_cnt + set*NN;
    for (int i = t; i < 2048; i += 1024) s[i] = (i < NN) ? cnt[i] : 0;
    __syncthreads();
    for (int i = t; i < NN; i += 1024)
        g_dinv[set*NN + i] = rsqrtf((float)(cnt[i] + 1));
    for (int off = 1; off < 2048; off <<= 1) {
        int v0 = (t >= off) ? s[t - off] : 0;
        int i1 = t + 1024;
        int v1 = s[i1 - off];
        __syncthreads();
        s[t] += v0; s[i1] += v1;
        __syncthreads();
    }
    int* ptr = g_ptr + set*(NN+1);
    for (int i = t; i <= NN; i += 1024) ptr[i] = (i == 0) ? 0 : s[i-1];
}
__global__ void k_fill(const int* __restrict__ row, const int* __restrict__ col, int E, int set) {
    int e = blockIdx.x*blockDim.x + threadIdx.x;
    if (e >= E) return;
    int r = row[e], c = col[e];
    float nrm = g_dinv[set*NN + r] * g_dinv[set*NN + c];
    int pos = g_ptr[set*(NN+1) + c] + atomicAdd(&g_cur[set*NN + c], 1);
    g_esrc [set*MAXE + pos] = r;
    g_enorm[set*MAXE + pos] = nrm;
}

// ---------------- bf16 hi/lo split ----------------
__device__ __forceinline__ void split4(float4 v, uint2& hi, uint2& lo) {
    __nv_bfloat16 h0 = __float2bfloat16(v.x), h1 = __float2bfloat16(v.y),
                  h2 = __float2bfloat16(v.z), h3 = __float2bfloat16(v.w);
    __nv_bfloat16 l0 = __float2bfloat16(v.x - __bfloat162float(h0));
    __nv_bfloat16 l1 = __float2bfloat16(v.y - __bfloat162float(h1));
    __nv_bfloat16 l2 = __float2bfloat16(v.z - __bfloat162float(h2));
    __nv_bfloat16 l3 = __float2bfloat16(v.w - __bfloat162float(h3));
    __nv_bfloat162 hA = __nv_bfloat162(h0, h1), hB = __nv_bfloat162(h2, h3);
    __nv_bfloat162 lA = __nv_bfloat162(l0, l1), lB = __nv_bfloat162(l2, l3);
    hi.x = *(uint32_t*)&hA; hi.y = *(uint32_t*)&hB;
    lo.x = *(uint32_t*)&lA; lo.y = *(uint32_t*)&lB;
}

// x fp32 [M,256] -> hi/lo images: [tile][chunk(8)][128x32 swizzled]
__global__ __launch_bounds__(256) void k_convA(const float* __restrict__ X) {
    int idx = blockIdx.x * 256 + threadIdx.x;
    int m = idx >> 6, lane = idx & 63;
    if (m >= MTOT) return;
    int k = lane * 4;
    float4 v = *(const float4*)&X[(size_t)m * CC + k];
    uint2 hi, lo; split4(v, hi, lo);
    int tile = m >> 7, mi = m & 127, chunk = k >> 5, kin = k & 31;
    size_t eo = (size_t)(tile*8 + chunk)*4096 + swz_elem(mi, kin);
    *(uint2*)(g_ah + eo) = hi;
    *(uint2*)(g_al + eo) = lo;
}

// W fp32 [k=256][n=256] -> hi/lo images: [nhalf(2)][chunk(8)][128x32 swizzled] (row=n, col=k)
__global__ __launch_bounds__(256) void k_convW(const float* __restrict__ W, int layer) {
    int idx = blockIdx.x * 256 + threadIdx.x;     // 64 blocks x 256
    int n = idx >> 6, kq = idx & 63;
    if (n >= 256) return;
    int k = kq * 4;
    float4 v = make_float4(W[(size_t)(k+0)*CC + n], W[(size_t)(k+1)*CC + n],
                           W[(size_t)(k+2)*CC + n], W[(size_t)(k+3)*CC + n]);
    uint2 hi, lo; split4(v, hi, lo);
    int nh = n >> 7, ni = n & 127, chunk = k >> 5, kin = k & 31;
    size_t eo = (size_t)layer*65536 + (size_t)(nh*8 + chunk)*4096 + swz_elem(ni, kin);
    *(uint2*)(g_bh + eo) = hi;
    *(uint2*)(g_bl + eo) = lo;
}

// ---------------- HMMA GEMM: H = A @ W via bf16 3-product split ----------------
// grid (850): CTA tile 128x256, 512 thr = 16 warps (4m x 4n), warp tile 32x64.
// dyn smem: 3 stages x 48KB {Ahi 8K | Alo 8K | Bhi 16K | Blo 16K}
#define GSTAGE 49152
#define GSM (3*GSTAGE)
__global__ __launch_bounds__(512) void k_gemm_mma(const __nv_bfloat16* __restrict__ Bh,
                                                  const __nv_bfloat16* __restrict__ Bl,
                                                  float* __restrict__ H) {
    extern __shared__ __align__(128) char smc[];
    uint32_t sb = smem_u32(smc);
    int tid = threadIdx.x, wid = tid >> 5, lane = tid & 31;
    int tile = blockIdx.x;
    int mwarp = (wid >> 2) * 32, nwarp = (wid & 3) * 64;

    const char* gAh = (const char*)(g_ah + (size_t)tile * 8 * 4096);
    const char* gAl = (const char*)(g_al + (size_t)tile * 8 * 4096);
    const char* gBh = (const char*)Bh;
    const char* gBl = (const char*)Bl;

    // ldmatrix address precompute
    int r15 = lane & 15, hi2 = lane >> 4;
    uint32_t aoff[2]; int asw[2];
    #pragma unroll
    for (int i = 0; i < 2; i++) {
        int mr = mwarp + i*16 + r15;
        aoff[i] = mr * 64; asw[i] = (mr >> 1) & 3;
    }
    uint32_t boff[4]; int bsw[4];
    uint32_t nhbase = (uint32_t)(nwarp >> 7) * 8192;
    #pragma unroll
    for (int j = 0; j < 4; j++) {
        int nr = (nwarp & 127) + j*16 + r15;
        boff[j] = nhbase + nr * 64; bsw[j] = (nr >> 1) & 3;
    }

    float d[2][8][4];
    #pragma unroll
    for (int i = 0; i < 2; i++)
        #pragma unroll
        for (int j = 0; j < 8; j++)
            #pragma unroll
            for (int q = 0; q < 4; q++) d[i][j][q] = 0.f;

    // stage copy: 6 x 16B per thread (A hi/lo 8KB each, B hi/lo 16KB each)
    #define ISSUE(c, st) do { \
        uint32_t so = sb + (uint32_t)(st) * GSTAGE; \
        uint32_t off = (uint32_t)tid * 16; \
        size_t ga = (size_t)(c) * 8192; \
        CPASYNC16(so +        off, gAh + ga + off); \
        CPASYNC16(so + 8192 + off, gAl + ga + off); \
        _Pragma("unroll") \
        for (int nh_ = 0; nh_ < 2; nh_++) { \
            size_t gb = (size_t)(nh_*8 + (c)) * 8192; \
            CPASYNC16(so + 16384 + nh_*8192 + off, gBh + gb + off); \
            CPASYNC16(so + 32768 + nh_*8192 + off, gBl + gb + off); \
        } \
        CPCOMMIT(); \
    } while (0)

    ISSUE(0, 0);
    ISSUE(1, 1);
    int st = 0;
    for (int c = 0; c < 8; c++) {
        if (c + 2 < 8) { ISSUE(c+2, (c+2)%3); CPWAIT(2); }
        else if (c == 6) { CPWAIT(1); }
        else if (c == 7) { CPWAIT(0); }
        __syncthreads();
        uint32_t base = sb + (uint32_t)st * GSTAGE;
        #pragma unroll
        for (int s = 0; s < 2; s++) {
            uint32_t ah[2][4], al[2][4];
            #pragma unroll
            for (int i = 0; i < 2; i++) {
                uint32_t kc = (uint32_t)((((s<<1)|hi2) ^ asw[i]) << 4);
                LDSM4(ah[i][0],ah[i][1],ah[i][2],ah[i][3], base + aoff[i] + kc);
                LDSM4(al[i][0],al[i][1],al[i][2],al[i][3], base + 8192 + aoff[i] + kc);
            }
            #pragma unroll
            for (int j = 0; j < 4; j++) {
                uint32_t kc = (uint32_t)((((s<<1)|hi2) ^ bsw[j]) << 4);
                uint32_t bh0,bh1,bh2,bh3, bl0,bl1,bl2,bl3;
                LDSM4(bh0,bh1,bh2,bh3, base + 16384 + boff[j] + kc);
                LDSM4(bl0,bl1,bl2,bl3, base + 32768 + boff[j] + kc);
                #pragma unroll
                for (int i = 0; i < 2; i++) {
                    MMA16816(d[i][2*j],   ah[i], bh0, bh2);
                    MMA16816(d[i][2*j+1], ah[i], bh1, bh3);
                    MMA16816(d[i][2*j],   ah[i], bl0, bl2);
                    MMA16816(d[i][2*j+1], ah[i], bl1, bl3);
                    MMA16816(d[i][2*j],   al[i], bh0, bh2);
                    MMA16816(d[i][2*j+1], al[i], bh1, bh3);
                }
            }
        }
        __syncthreads();
        st = (st + 1) % 3;
    }

    // epilogue: fp32 store
    int rr = lane >> 2, cp = (lane & 3) * 2;
    #pragma unroll
    for (int i = 0; i < 2; i++) {
        size_t row = (size_t)tile*128 + mwarp + i*16 + rr;
        #pragma unroll
        for (int j = 0; j < 8; j++) {
            int col = nwarp + j*8 + cp;
            float2 v0 = make_float2(d[i][j][0], d[i][j][1]);
            float2 v1 = make_float2(d[i][j][2], d[i][j][3]);
            *(float2*)&H[row*CC + col]     = v0;
            *(float2*)&H[(row+8)*CC + col] = v1;
        }
    }
}

// ---------------- aggregation ----------------
// acc = sum_in-edges norm*h[b,src,:] + dinv^2*h[b,n,:] + bias (+res), relu.
// block = 1 node x 4 batches (metadata shared); write_img -> hi/lo A images.
__global__ __launch_bounds__(256) void k_agg(const float* __restrict__ h, int set,
                                             const float* __restrict__ bias,
                                             const float* __restrict__ residual,
                                             float* __restrict__ out, int write_img) {
    int g    = threadIdx.x >> 6;           // batch sub-group 0..3
    int lane = threadIdx.x & 63;           // channel/4
    int n = blockIdx.x;
    int b = blockIdx.y * 4 + g;

    const int* ptr = g_ptr + set*(NN+1);
    int p0 = __ldg(&ptr[n]), p1 = __ldg(&ptr[n+1]);
    float dn = __ldg(&g_dinv[set*NN + n]);
    size_t bbase = (size_t)b * NN;
    size_t base  = (bbase + n) * CC + lane*4;

    float4 sv = *(const float4*)&h[base];
    float w = dn * dn;
    float4 acc;
    acc.x = w*sv.x; acc.y = w*sv.y; acc.z = w*sv.z; acc.w = w*sv.w;

    int off = set*MAXE;
    int j = p0;
    for (; j + 2 <= p1; j += 2) {
        int   s0 = __ldg(&g_esrc [off + j]);
        int   s1 = __ldg(&g_esrc [off + j + 1]);
        float w0 = __ldg(&g_enorm[off + j]);
        float w1 = __ldg(&g_enorm[off + j + 1]);
        float4 v0 = *(const float4*)&h[(bbase + s0)*CC + lane*4];
        float4 v1 = *(const float4*)&h[(bbase + s1)*CC + lane*4];
        acc.x += w0*v0.x + w1*v1.x;
        acc.y += w0*v0.y + w1*v1.y;
        acc.z += w0*v0.z + w1*v1.z;
        acc.w += w0*v0.w + w1*v1.w;
    }
    if (j < p1) {
        int   s0 = __ldg(&g_esrc [off + j]);
        float w0 = __ldg(&g_enorm[off + j]);
        float4 v0 = *(const float4*)&h[(bbase + s0)*CC + lane*4];
        acc.x += w0*v0.x; acc.y += w0*v0.y; acc.z += w0*v0.z; acc.w += w0*v0.w;
    }

    float4 bi = *(const float4*)&bias[lane*4];
    acc.x += bi.x; acc.y += bi.y; acc.z += bi.z; acc.w += bi.w;
    if (residual) {
        float4 rv = *(const float4*)&residual[base];
        acc.x += rv.x; acc.y += rv.y; acc.z += rv.z; acc.w += rv.w;
    }
    acc.x = fmaxf(acc.x, 0.f); acc.y = fmaxf(acc.y, 0.f);
    acc.z = fmaxf(acc.z, 0.f); acc.w = fmaxf(acc.w, 0.f);

    if (write_img) {
        uint2 hi, lo; split4(acc, hi, lo);
        int m = (int)(bbase + n);
        int tile = m >> 7, mi = m & 127, k = lane*4, chunk = k >> 5, kin = k & 31;
        size_t eo = (size_t)(tile*8 + chunk)*4096 + swz_elem(mi, kin);
        *(uint2*)(g_ah + eo) = hi;
        *(uint2*)(g_al + eo) = lo;
    } else {
        *(float4*)&out[base] = acc;
    }
}

// ---------------- launch ----------------
extern "C" void kernel_launch(void* const* d_in, const int* in_sizes, int n_in,
                              void* d_out, int out_size) {
    const float* x  = (const float*)d_in[0];
    const float* W1 = (const float*)d_in[1];
    const float* b1 = (const float*)d_in[2];
    const float* W2 = (const float*)d_in[3];
    const float* b2 = (const float*)d_in[4];
    const float* W3 = (const float*)d_in[5];
    const float* b3 = (const float*)d_in[6];
    const int*   sp = (const int*)d_in[7];
    const int*   tm = (const int*)d_in[8];
    int Esp = in_sizes[7] / 2;
    int Etm = in_sizes[8] / 2;
    float* out = (float*)d_out;

    float* h; __nv_bfloat16 *bh, *bl;
    cudaGetSymbolAddress((void**)&h,  g_h);
    cudaGetSymbolAddress((void**)&bh, g_bh);
    cudaGetSymbolAddress((void**)&bl, g_bl);

    cudaFuncSetAttribute(k_gemm_mma, cudaFuncAttributeMaxDynamicSharedMemorySize, GSM);

    dim3 ga(NN, BB/4);                // (1700, 16)

    // conversions + prep
    k_convA<<<(MTOT*64 + 255)/256, 256>>>(x);
    k_convW<<<64, 256>>>(W1, 0);
    k_convW<<<64, 256>>>(W2, 1);
    k_convW<<<64, 256>>>(W3, 2);
    k_init <<<(2*NN + 255)/256, 256>>>();
    k_count<<<(Esp + 255)/256, 256>>>(sp + Esp, Esp, 0);
    k_count<<<(Etm + 255)/256, 256>>>(tm + Etm, Etm, 1);
    k_scan <<<1, 1024>>>(0);
    k_scan <<<1, 1024>>>(1);
    k_fill <<<(Esp + 255)/256, 256>>>(sp, sp + Esp, Esp, 0);
    k_fill <<<(Etm + 255)/256, 256>>>(tm, tm + Etm, Etm, 1);

    // conv1: relu(agg_sp(x@W1)+b1) -> images
    k_gemm_mma<<<MTILES, 512, GSM>>>(bh, bl, h);
    k_agg<<<ga, 256>>>(h, 0, b1, nullptr, nullptr, 1);
    // conv2: relu(agg_tm(.@W2)+b2) -> images
    k_gemm_mma<<<MTILES, 512, GSM>>>(bh + 65536, bl + 65536, h);
    k_agg<<<ga, 256>>>(h, 1, b2, nullptr, nullptr, 1);
    // conv3: relu(agg_sp(.@W3)+b3+x) -> out
    k_gemm_mma<<<MTILES, 512, GSM>>>(bh + 2*65536, bl + 2*65536, h);
    k_agg<<<ga, 256>>>(h, 0, b3, x, out, 0);
}

// round 6
// speedup vs baseline: 2.6106x; 1.0143x over previous
#include <cuda_runtime.h>
#include <cuda_bf16.h>
#include <cstdint>

typedef unsigned long long ull;

#define BB 64
#define NN 1700
#define CC 256
#define MAXE 16384
#define MTOT (BB*NN)
#define MTILES (MTOT/128)          // 850

// ---------------- scratch (device globals; no allocation allowed) ----------------
__device__ float g_h[(size_t)BB*NN*CC];                    // GEMM output (fp32)
__device__ __nv_bfloat16 g_ah[(size_t)MTOT*CC];            // A hi image (chunked+swizzled)
__device__ __nv_bfloat16 g_al[(size_t)MTOT*CC];            // A lo image
__device__ __nv_bfloat16 g_bh[3*65536];                    // B hi images per layer
__device__ __nv_bfloat16 g_bl[3*65536];                    // B lo images per layer
__device__ int   g_cnt[2*NN];
__device__ int   g_cur[2*NN];
__device__ int   g_ptr[2*(NN+1)];
__device__ float g_dinv[2*NN];
__device__ int   g_esrc[2*MAXE];
__device__ float g_enorm[2*MAXE];

// ---------------- PTX helpers (all sm_80-class: valid for compute_103) ----------------
__device__ __forceinline__ uint32_t smem_u32(const void* p) {
    uint32_t a;
    asm("{ .reg .u64 t; cvta.to.shared.u64 t, %1; cvt.u32.u64 %0, t; }" : "=r"(a) : "l"(p));
    return a;
}
#define LDSM4(r0,r1,r2,r3,addr) \
    asm volatile("ldmatrix.sync.aligned.m8n8.x4.shared.b16 {%0,%1,%2,%3}, [%4];" \
        : "=r"(r0),"=r"(r1),"=r"(r2),"=r"(r3) : "r"(addr))
#define MMA16816(d, a, b0, b1) \
    asm volatile("mma.sync.aligned.m16n8k16.row.col.f32.bf16.bf16.f32 " \
        "{%0,%1,%2,%3},{%4,%5,%6,%7},{%8,%9},{%0,%1,%2,%3};" \
        : "+f"((d)[0]),"+f"((d)[1]),"+f"((d)[2]),"+f"((d)[3]) \
        : "r"((a)[0]),"r"((a)[1]),"r"((a)[2]),"r"((a)[3]), "r"(b0),"r"(b1))
#define CPASYNC16(dst, src) \
    asm volatile("cp.async.cg.shared.global [%0], [%1], 16;" :: "r"(dst), "l"(src))
#define CPCOMMIT() asm volatile("cp.async.commit_group;")
#define CPWAIT(n)  asm volatile("cp.async.wait_group %0;" :: "n"(n))

// chunked image element offset within a 128x32 block, 16B-chunk XOR swizzle:
// row r (0..127, 64B/row), kin (0..31): kc' = (kin>>3) ^ ((r>>1)&3)
__device__ __forceinline__ uint32_t swz_elem(int r, int kin) {
    return (uint32_t)(r*32 + ((((kin>>3) ^ ((r>>1)&3)))<<3) + (kin&7));
}

// ---------------- prep kernels ----------------
__global__ void k_init() {
    int i = blockIdx.x*blockDim.x + threadIdx.x;
    if (i < 2*NN) { g_cnt[i] = 0; g_cur[i] = 0; }
}
__global__ void k_count(const int* __restrict__ col, int E, int set) {
    int e = blockIdx.x*blockDim.x + threadIdx.x;
    if (e < E) atomicAdd(&g_cnt[set*NN + col[e]], 1);
}
__global__ void k_scan(int set) {
    __shared__ int s[2048];
    int t = threadIdx.x;
    const int* cnt = g_cnt + set*NN;
    for (int i = t; i < 2048; i += 1024) s[i] = (i < NN) ? cnt[i] : 0;
    __syncthreads();
    for (int i = t; i < NN; i += 1024)
        g_dinv[set*NN + i] = rsqrtf((float)(cnt[i] + 1));
    for (int off = 1; off < 2048; off <<= 1) {
        int v0 = (t >= off) ? s[t - off] : 0;
        int i1 = t + 1024;
        int v1 = s[i1 - off];
        __syncthreads();
        s[t] += v0; s[i1] += v1;
        __syncthreads();
    }
    int* ptr = g_ptr + set*(NN+1);
    for (int i = t; i <= NN; i += 1024) ptr[i] = (i == 0) ? 0 : s[i-1];
}
__global__ void k_fill(const int* __restrict__ row, const int* __restrict__ col, int E, int set) {
    int e = blockIdx.x*blockDim.x + threadIdx.x;
    if (e >= E) return;
    int r = row[e], c = col[e];
    float nrm = g_dinv[set*NN + r] * g_dinv[set*NN + c];
    int pos = g_ptr[set*(NN+1) + c] + atomicAdd(&g_cur[set*NN + c], 1);
    g_esrc [set*MAXE + pos] = r;
    g_enorm[set*MAXE + pos] = nrm;
}

// ---------------- bf16 hi/lo split ----------------
__device__ __forceinline__ void split4(float4 v, uint2& hi, uint2& lo) {
    __nv_bfloat16 h0 = __float2bfloat16(v.x), h1 = __float2bfloat16(v.y),
                  h2 = __float2bfloat16(v.z), h3 = __float2bfloat16(v.w);
    __nv_bfloat16 l0 = __float2bfloat16(v.x - __bfloat162float(h0));
    __nv_bfloat16 l1 = __float2bfloat16(v.y - __bfloat162float(h1));
    __nv_bfloat16 l2 = __float2bfloat16(v.z - __bfloat162float(h2));
    __nv_bfloat16 l3 = __float2bfloat16(v.w - __bfloat162float(h3));
    __nv_bfloat162 hA = __nv_bfloat162(h0, h1), hB = __nv_bfloat162(h2, h3);
    __nv_bfloat162 lA = __nv_bfloat162(l0, l1), lB = __nv_bfloat162(l2, l3);
    hi.x = *(uint32_t*)&hA; hi.y = *(uint32_t*)&hB;
    lo.x = *(uint32_t*)&lA; lo.y = *(uint32_t*)&lB;
}

// x fp32 [M,256] -> hi/lo images: [tile][chunk(8)][128x32 swizzled]
__global__ __launch_bounds__(256) void k_convA(const float* __restrict__ X) {
    int idx = blockIdx.x * 256 + threadIdx.x;
    int m = idx >> 6, lane = idx & 63;
    if (m >= MTOT) return;
    int k = lane * 4;
    float4 v = *(const float4*)&X[(size_t)m * CC + k];
    uint2 hi, lo; split4(v, hi, lo);
    int tile = m >> 7, mi = m & 127, chunk = k >> 5, kin = k & 31;
    size_t eo = (size_t)(tile*8 + chunk)*4096 + swz_elem(mi, kin);
    *(uint2*)(g_ah + eo) = hi;
    *(uint2*)(g_al + eo) = lo;
}

// W fp32 [k=256][n=256] -> hi/lo images: [nhalf(2)][chunk(8)][128x32 swizzled] (row=n, col=k)
__global__ __launch_bounds__(256) void k_convW(const float* __restrict__ W, int layer) {
    int idx = blockIdx.x * 256 + threadIdx.x;     // 64 blocks x 256
    int n = idx >> 6, kq = idx & 63;
    if (n >= 256) return;
    int k = kq * 4;
    float4 v = make_float4(W[(size_t)(k+0)*CC + n], W[(size_t)(k+1)*CC + n],
                           W[(size_t)(k+2)*CC + n], W[(size_t)(k+3)*CC + n]);
    uint2 hi, lo; split4(v, hi, lo);
    int nh = n >> 7, ni = n & 127, chunk = k >> 5, kin = k & 31;
    size_t eo = (size_t)layer*65536 + (size_t)(nh*8 + chunk)*4096 + swz_elem(ni, kin);
    *(uint2*)(g_bh + eo) = hi;
    *(uint2*)(g_bl + eo) = lo;
}

// ---------------- HMMA GEMM: H = A @ W via bf16 3-product split ----------------
// grid (850): CTA tile 128x256, 512 thr = 16 warps (4m x 4n), warp tile 32x64.
// dyn smem: 4 stages x 48KB {Ahi 8K | Alo 8K | Bhi 16K | Blo 16K}
#define GSTAGE 49152
#define GSM (4*GSTAGE)
__global__ __launch_bounds__(512) void k_gemm_mma(const __nv_bfloat16* __restrict__ Bh,
                                                  const __nv_bfloat16* __restrict__ Bl,
                                                  float* __restrict__ H) {
    extern __shared__ __align__(128) char smc[];
    uint32_t sb = smem_u32(smc);
    int tid = threadIdx.x, wid = tid >> 5, lane = tid & 31;
    int tile = blockIdx.x;
    int mwarp = (wid >> 2) * 32, nwarp = (wid & 3) * 64;

    const char* gAh = (const char*)(g_ah + (size_t)tile * 8 * 4096);
    const char* gAl = (const char*)(g_al + (size_t)tile * 8 * 4096);
    const char* gBh = (const char*)Bh;
    const char* gBl = (const char*)Bl;

    // ldmatrix address precompute
    int r15 = lane & 15, hi2 = lane >> 4;
    uint32_t aoff[2]; int asw[2];
    #pragma unroll
    for (int i = 0; i < 2; i++) {
        int mr = mwarp + i*16 + r15;
        aoff[i] = mr * 64; asw[i] = (mr >> 1) & 3;
    }
    uint32_t boff[4]; int bsw[4];
    uint32_t nhbase = (uint32_t)(nwarp >> 7) * 8192;
    #pragma unroll
    for (int j = 0; j < 4; j++) {
        int nr = (nwarp & 127) + j*16 + r15;
        boff[j] = nhbase + nr * 64; bsw[j] = (nr >> 1) & 3;
    }

    float d[2][8][4];
    #pragma unroll
    for (int i = 0; i < 2; i++)
        #pragma unroll
        for (int j = 0; j < 8; j++)
            #pragma unroll
            for (int q = 0; q < 4; q++) d[i][j][q] = 0.f;

    // stage copy: 6 x 16B per thread (A hi/lo 8KB each, B hi/lo 16KB each)
    #define ISSUE(c, st) do { \
        uint32_t so = sb + (uint32_t)(st) * GSTAGE; \
        uint32_t off = (uint32_t)tid * 16; \
        size_t ga = (size_t)(c) * 8192; \
        CPASYNC16(so +        off, gAh + ga + off); \
        CPASYNC16(so + 8192 + off, gAl + ga + off); \
        _Pragma("unroll") \
        for (int nh_ = 0; nh_ < 2; nh_++) { \
            size_t gb = (size_t)(nh_*8 + (c)) * 8192; \
            CPASYNC16(so + 16384 + nh_*8192 + off, gBh + gb + off); \
            CPASYNC16(so + 32768 + nh_*8192 + off, gBl + gb + off); \
        } \
        CPCOMMIT(); \
    } while (0)

    ISSUE(0, 0);
    ISSUE(1, 1);
    ISSUE(2, 2);
    for (int c = 0; c < 8; c++) {
        if (c <= 5)      { CPWAIT(2); }
        else if (c == 6) { CPWAIT(1); }
        else             { CPWAIT(0); }
        __syncthreads();                       // single barrier per iteration
        uint32_t base = sb + (uint32_t)(c & 3) * GSTAGE;
        #pragma unroll
        for (int s = 0; s < 2; s++) {
            uint32_t ah[2][4], al[2][4];
            #pragma unroll
            for (int i = 0; i < 2; i++) {
                uint32_t kc = (uint32_t)((((s<<1)|hi2) ^ asw[i]) << 4);
                LDSM4(ah[i][0],ah[i][1],ah[i][2],ah[i][3], base + aoff[i] + kc);
                LDSM4(al[i][0],al[i][1],al[i][2],al[i][3], base + 8192 + aoff[i] + kc);
            }
            #pragma unroll
            for (int j = 0; j < 4; j++) {
                uint32_t kc = (uint32_t)((((s<<1)|hi2) ^ bsw[j]) << 4);
                uint32_t bh0,bh1,bh2,bh3, bl0,bl1,bl2,bl3;
                LDSM4(bh0,bh1,bh2,bh3, base + 16384 + boff[j] + kc);
                LDSM4(bl0,bl1,bl2,bl3, base + 32768 + boff[j] + kc);
                #pragma unroll
                for (int i = 0; i < 2; i++) {
                    MMA16816(d[i][2*j],   ah[i], bh0, bh2);
                    MMA16816(d[i][2*j+1], ah[i], bh1, bh3);
                    MMA16816(d[i][2*j],   ah[i], bl0, bl2);
                    MMA16816(d[i][2*j+1], ah[i], bl1, bl3);
                    MMA16816(d[i][2*j],   al[i], bh0, bh2);
                    MMA16816(d[i][2*j+1], al[i], bh1, bh3);
                }
            }
        }
        if (c + 3 < 8) ISSUE(c+3, (c+3) & 3);  // writes buf (c-1)&3: all readers passed this iter's barrier
    }

    // epilogue: fp32 store
    int rr = lane >> 2, cp = (lane & 3) * 2;
    #pragma unroll
    for (int i = 0; i < 2; i++) {
        size_t row = (size_t)tile*128 + mwarp + i*16 + rr;
        #pragma unroll
        for (int j = 0; j < 8; j++) {
            int col = nwarp + j*8 + cp;
            float2 v0 = make_float2(d[i][j][0], d[i][j][1]);
            float2 v1 = make_float2(d[i][j][2], d[i][j][3]);
            *(float2*)&H[row*CC + col]     = v0;
            *(float2*)&H[(row+8)*CC + col] = v1;
        }
    }
}

// ---------------- aggregation ----------------
// acc = sum_in-edges norm*h[b,src,:] + dinv^2*h[b,n,:] + bias (+res), relu.
// block = 1 node x 4 batches (metadata shared); write_img -> hi/lo A images.
__global__ __launch_bounds__(256) void k_agg(const float* __restrict__ h, int set,
                                             const float* __restrict__ bias,
                                             const float* __restrict__ residual,
                                             float* __restrict__ out, int write_img) {
    int g    = threadIdx.x >> 6;           // batch sub-group 0..3
    int lane = threadIdx.x & 63;           // channel/4
    int n = blockIdx.x;
    int b = blockIdx.y * 4 + g;

    const int* ptr = g_ptr + set*(NN+1);
    int p0 = __ldg(&ptr[n]), p1 = __ldg(&ptr[n+1]);
    float dn = __ldg(&g_dinv[set*NN + n]);
    size_t bbase = (size_t)b * NN;
    size_t base  = (bbase + n) * CC + lane*4;

    float4 sv = *(const float4*)&h[base];
    float w = dn * dn;
    float4 acc;
    acc.x = w*sv.x; acc.y = w*sv.y; acc.z = w*sv.z; acc.w = w*sv.w;

    int off = set*MAXE;
    int j = p0;
    for (; j + 4 <= p1; j += 4) {
        int   s0 = __ldg(&g_esrc [off + j]);
        int   s1 = __ldg(&g_esrc [off + j + 1]);
        int   s2 = __ldg(&g_esrc [off + j + 2]);
        int   s3 = __ldg(&g_esrc [off + j + 3]);
        float w0 = __ldg(&g_enorm[off + j]);
        float w1 = __ldg(&g_enorm[off + j + 1]);
        float w2 = __ldg(&g_enorm[off + j + 2]);
        float w3 = __ldg(&g_enorm[off + j + 3]);
        float4 v0 = *(const float4*)&h[(bbase + s0)*CC + lane*4];
        float4 v1 = *(const float4*)&h[(bbase + s1)*CC + lane*4];
        float4 v2 = *(const float4*)&h[(bbase + s2)*CC + lane*4];
        float4 v3 = *(const float4*)&h[(bbase + s3)*CC + lane*4];
        acc.x += w0*v0.x + w1*v1.x + w2*v2.x + w3*v3.x;
        acc.y += w0*v0.y + w1*v1.y + w2*v2.y + w3*v3.y;
        acc.z += w0*v0.z + w1*v1.z + w2*v2.z + w3*v3.z;
        acc.w += w0*v0.w + w1*v1.w + w2*v2.w + w3*v3.w;
    }
    for (; j < p1; ++j) {
        int   s0 = __ldg(&g_esrc [off + j]);
        float w0 = __ldg(&g_enorm[off + j]);
        float4 v0 = *(const float4*)&h[(bbase + s0)*CC + lane*4];
        acc.x += w0*v0.x; acc.y += w0*v0.y; acc.z += w0*v0.z; acc.w += w0*v0.w;
    }

    float4 bi = *(const float4*)&bias[lane*4];
    acc.x += bi.x; acc.y += bi.y; acc.z += bi.z; acc.w += bi.w;
    if (residual) {
        float4 rv = *(const float4*)&residual[base];
        acc.x += rv.x; acc.y += rv.y; acc.z += rv.z; acc.w += rv.w;
    }
    acc.x = fmaxf(acc.x, 0.f); acc.y = fmaxf(acc.y, 0.f);
    acc.z = fmaxf(acc.z, 0.f); acc.w = fmaxf(acc.w, 0.f);

    if (write_img) {
        uint2 hi, lo; split4(acc, hi, lo);
        int m = (int)(bbase + n);
        int tile = m >> 7, mi = m & 127, k = lane*4, chunk = k >> 5, kin = k & 31;
        size_t eo = (size_t)(tile*8 + chunk)*4096 + swz_elem(mi, kin);
        *(uint2*)(g_ah + eo) = hi;
        *(uint2*)(g_al + eo) = lo;
    } else {
        *(float4*)&out[base] = acc;
    }
}

// ---------------- launch ----------------
extern "C" void kernel_launch(void* const* d_in, const int* in_sizes, int n_in,
                              void* d_out, int out_size) {
    const float* x  = (const float*)d_in[0];
    const float* W1 = (const float*)d_in[1];
    const float* b1 = (const float*)d_in[2];
    const float* W2 = (const float*)d_in[3];
    const float* b2 = (const float*)d_in[4];
    const float* W3 = (const float*)d_in[5];
    const float* b3 = (const float*)d_in[6];
    const int*   sp = (const int*)d_in[7];
    const int*   tm = (const int*)d_in[8];
    int Esp = in_sizes[7] / 2;
    int Etm = in_sizes[8] / 2;
    float* out = (float*)d_out;

    float* h; __nv_bfloat16 *bh, *bl;
    cudaGetSymbolAddress((void**)&h,  g_h);
    cudaGetSymbolAddress((void**)&bh, g_bh);
    cudaGetSymbolAddress((void**)&bl, g_bl);

    cudaFuncSetAttribute(k_gemm_mma, cudaFuncAttributeMaxDynamicSharedMemorySize, GSM);

    dim3 ga(NN, BB/4);                // (1700, 16)

    // conversions; GEMM1 early so the ncu sample slot lands on it
    k_convA<<<(MTOT*64 + 255)/256, 256>>>(x);
    k_convW<<<64, 256>>>(W1, 0);
    k_gemm_mma<<<MTILES, 512, GSM>>>(bh, bl, h);
    k_convW<<<64, 256>>>(W2, 1);
    k_convW<<<64, 256>>>(W3, 2);

    // graph prep
    k_init <<<(2*NN + 255)/256, 256>>>();
    k_count<<<(Esp + 255)/256, 256>>>(sp + Esp, Esp, 0);
    k_count<<<(Etm + 255)/256, 256>>>(tm + Etm, Etm, 1);
    k_scan <<<1, 1024>>>(0);
    k_scan <<<1, 1024>>>(1);
    k_fill <<<(Esp + 255)/256, 256>>>(sp, sp + Esp, Esp, 0);
    k_fill <<<(Etm + 255)/256, 256>>>(tm, tm + Etm, Etm, 1);

    // conv1: relu(agg_sp(x@W1)+b1) -> images
    k_agg<<<ga, 256>>>(h, 0, b1, nullptr, nullptr, 1);
    // conv2: relu(agg_tm(.@W2)+b2) -> images
    k_gemm_mma<<<MTILES, 512, GSM>>>(bh + 65536, bl + 65536, h);
    k_agg<<<ga, 256>>>(h, 1, b2, nullptr, nullptr, 1);
    // conv3: relu(agg_sp(.@W3)+b3+x) -> out
    k_gemm_mma<<<MTILES, 512, GSM>>>(bh + 2*65536, bl + 2*65536, h);
    k_agg<<<ga, 256>>>(h, 0, b3, x, out, 0);
}

// round 7
// speedup vs baseline: 2.6245x; 1.0053x over previous
#include <cuda_runtime.h>
#include <cuda_bf16.h>
#include <cstdint>

typedef unsigned long long ull;

#define BB 64
#define NN 1700
#define CC 256
#define MAXE 16384
#define MTOT (BB*NN)
#define MTILES (MTOT/128)          // 850

// ---------------- scratch (device globals; no allocation allowed) ----------------
__device__ float g_h[(size_t)BB*NN*CC];                    // GEMM output (fp32)
__device__ __nv_bfloat16 g_ah[(size_t)MTOT*CC];            // A hi image (chunked+swizzled)
__device__ __nv_bfloat16 g_al[(size_t)MTOT*CC];            // A lo image
__device__ __nv_bfloat16 g_bh[3*65536];                    // B hi images per layer
__device__ __nv_bfloat16 g_bl[3*65536];                    // B lo images per layer
__device__ int   g_cnt[2*NN];
__device__ int   g_cur[2*NN];
__device__ int   g_ptr[2*(NN+1)];
__device__ float g_dinv[2*NN];
__device__ int   g_esrc[2*MAXE];
__device__ float g_enorm[2*MAXE];

// ---------------- PTX helpers (all sm_80-class: valid for compute_103) ----------------
__device__ __forceinline__ uint32_t smem_u32(const void* p) {
    uint32_t a;
    asm("{ .reg .u64 t; cvta.to.shared.u64 t, %1; cvt.u32.u64 %0, t; }" : "=r"(a) : "l"(p));
    return a;
}
#define LDSM4(r0,r1,r2,r3,addr) \
    asm volatile("ldmatrix.sync.aligned.m8n8.x4.shared.b16 {%0,%1,%2,%3}, [%4];" \
        : "=r"(r0),"=r"(r1),"=r"(r2),"=r"(r3) : "r"(addr))
#define MMA16816(d, a, b0, b1) \
    asm volatile("mma.sync.aligned.m16n8k16.row.col.f32.bf16.bf16.f32 " \
        "{%0,%1,%2,%3},{%4,%5,%6,%7},{%8,%9},{%0,%1,%2,%3};" \
        : "+f"((d)[0]),"+f"((d)[1]),"+f"((d)[2]),"+f"((d)[3]) \
        : "r"((a)[0]),"r"((a)[1]),"r"((a)[2]),"r"((a)[3]), "r"(b0),"r"(b1))
#define CPASYNC16(dst, src) \
    asm volatile("cp.async.cg.shared.global [%0], [%1], 16;" :: "r"(dst), "l"(src))
#define CPCOMMIT() asm volatile("cp.async.commit_group;")
#define CPWAIT(n)  asm volatile("cp.async.wait_group %0;" :: "n"(n))

// chunked image element offset within a 128x32 block, 16B-chunk XOR swizzle:
// row r (0..127, 64B/row), kin (0..31): kc' = (kin>>3) ^ ((r>>1)&3)
__device__ __forceinline__ uint32_t swz_elem(int r, int kin) {
    return (uint32_t)(r*32 + ((((kin>>3) ^ ((r>>1)&3)))<<3) + (kin&7));
}

// ---------------- prep kernels ----------------
__global__ void k_init() {
    int i = blockIdx.x*blockDim.x + threadIdx.x;
    if (i < 2*NN) { g_cnt[i] = 0; g_cur[i] = 0; }
}
__global__ void k_count(const int* __restrict__ col, int E, int set) {
    int e = blockIdx.x*blockDim.x + threadIdx.x;
    if (e < E) atomicAdd(&g_cnt[set*NN + col[e]], 1);
}
__global__ void k_scan(int set) {
    __shared__ int s[2048];
    int t = threadIdx.x;
    const int* cnt = g_cnt + set*NN;
    for (int i = t; i < 2048; i += 1024) s[i] = (i < NN) ? cnt[i] : 0;
    __syncthreads();
    for (int i = t; i < NN; i += 1024)
        g_dinv[set*NN + i] = rsqrtf((float)(cnt[i] + 1));
    for (int off = 1; off < 2048; off <<= 1) {
        int v0 = (t >= off) ? s[t - off] : 0;
        int i1 = t + 1024;
        int v1 = s[i1 - off];
        __syncthreads();
        s[t] += v0; s[i1] += v1;
        __syncthreads();
    }
    int* ptr = g_ptr + set*(NN+1);
    for (int i = t; i <= NN; i += 1024) ptr[i] = (i == 0) ? 0 : s[i-1];
}
__global__ void k_fill(const int* __restrict__ row, const int* __restrict__ col, int E, int set) {
    int e = blockIdx.x*blockDim.x + threadIdx.x;
    if (e >= E) return;
    int r = row[e], c = col[e];
    float nrm = g_dinv[set*NN + r] * g_dinv[set*NN + c];
    int pos = g_ptr[set*(NN+1) + c] + atomicAdd(&g_cur[set*NN + c], 1);
    g_esrc [set*MAXE + pos] = r;
    g_enorm[set*MAXE + pos] = nrm;
}

// ---------------- bf16 hi/lo split ----------------
__device__ __forceinline__ void split4(float4 v, uint2& hi, uint2& lo) {
    __nv_bfloat16 h0 = __float2bfloat16(v.x), h1 = __float2bfloat16(v.y),
                  h2 = __float2bfloat16(v.z), h3 = __float2bfloat16(v.w);
    __nv_bfloat16 l0 = __float2bfloat16(v.x - __bfloat162float(h0));
    __nv_bfloat16 l1 = __float2bfloat16(v.y - __bfloat162float(h1));
    __nv_bfloat16 l2 = __float2bfloat16(v.z - __bfloat162float(h2));
    __nv_bfloat16 l3 = __float2bfloat16(v.w - __bfloat162float(h3));
    __nv_bfloat162 hA = __nv_bfloat162(h0, h1), hB = __nv_bfloat162(h2, h3);
    __nv_bfloat162 lA = __nv_bfloat162(l0, l1), lB = __nv_bfloat162(l2, l3);
    hi.x = *(uint32_t*)&hA; hi.y = *(uint32_t*)&hB;
    lo.x = *(uint32_t*)&lA; lo.y = *(uint32_t*)&lB;
}

// x fp32 [M,256] -> hi/lo images: [tile][chunk(8)][128x32 swizzled]
__global__ __launch_bounds__(256) void k_convA(const float* __restrict__ X) {
    int idx = blockIdx.x * 256 + threadIdx.x;
    int m = idx >> 6, lane = idx & 63;
    if (m >= MTOT) return;
    int k = lane * 4;
    float4 v = *(const float4*)&X[(size_t)m * CC + k];
    uint2 hi, lo; split4(v, hi, lo);
    int tile = m >> 7, mi = m & 127, chunk = k >> 5, kin = k & 31;
    size_t eo = (size_t)(tile*8 + chunk)*4096 + swz_elem(mi, kin);
    *(uint2*)(g_ah + eo) = hi;
    *(uint2*)(g_al + eo) = lo;
}

// W fp32 [k=256][n=256] -> hi/lo images: [nhalf(2)][chunk(8)][128x32 swizzled] (row=n, col=k)
__global__ __launch_bounds__(256) void k_convW(const float* __restrict__ W, int layer) {
    int idx = blockIdx.x * 256 + threadIdx.x;     // 64 blocks x 256
    int n = idx >> 6, kq = idx & 63;
    if (n >= 256) return;
    int k = kq * 4;
    float4 v = make_float4(W[(size_t)(k+0)*CC + n], W[(size_t)(k+1)*CC + n],
                           W[(size_t)(k+2)*CC + n], W[(size_t)(k+3)*CC + n]);
    uint2 hi, lo; split4(v, hi, lo);
    int nh = n >> 7, ni = n & 127, chunk = k >> 5, kin = k & 31;
    size_t eo = (size_t)layer*65536 + (size_t)(nh*8 + chunk)*4096 + swz_elem(ni, kin);
    *(uint2*)(g_bh + eo) = hi;
    *(uint2*)(g_bl + eo) = lo;
}

// ---------------- HMMA GEMM: H = A @ W via bf16 3-product split ----------------
// grid (850): CTA tile 128x256, 512 thr = 16 warps (4m x 4n), warp tile 32x64.
// dyn smem: 4 stages x 48KB {Ahi 8K | Alo 8K | Bhi 16K | Blo 16K}
// MMA schedule grouped by product type: accumulator reuse distance 8 (breaks RAW chains).
#define GSTAGE 49152
#define GSM (4*GSTAGE)
__global__ __launch_bounds__(512) void k_gemm_mma(const __nv_bfloat16* __restrict__ Bh,
                                                  const __nv_bfloat16* __restrict__ Bl,
                                                  float* __restrict__ H) {
    extern __shared__ __align__(128) char smc[];
    uint32_t sb = smem_u32(smc);
    int tid = threadIdx.x, wid = tid >> 5, lane = tid & 31;
    int tile = blockIdx.x;
    int mwarp = (wid >> 2) * 32, nwarp = (wid & 3) * 64;

    const char* gAh = (const char*)(g_ah + (size_t)tile * 8 * 4096);
    const char* gAl = (const char*)(g_al + (size_t)tile * 8 * 4096);
    const char* gBh = (const char*)Bh;
    const char* gBl = (const char*)Bl;

    // ldmatrix address precompute
    int r15 = lane & 15, hi2 = lane >> 4;
    uint32_t aoff[2]; int asw[2];
    #pragma unroll
    for (int i = 0; i < 2; i++) {
        int mr = mwarp + i*16 + r15;
        aoff[i] = mr * 64; asw[i] = (mr >> 1) & 3;
    }
    uint32_t boff[4]; int bsw[4];
    uint32_t nhbase = (uint32_t)(nwarp >> 7) * 8192;
    #pragma unroll
    for (int j = 0; j < 4; j++) {
        int nr = (nwarp & 127) + j*16 + r15;
        boff[j] = nhbase + nr * 64; bsw[j] = (nr >> 1) & 3;
    }

    float d[2][8][4];
    #pragma unroll
    for (int i = 0; i < 2; i++)
        #pragma unroll
        for (int j = 0; j < 8; j++)
            #pragma unroll
            for (int q = 0; q < 4; q++) d[i][j][q] = 0.f;

    // stage copy: 6 x 16B per thread (A hi/lo 8KB each, B hi/lo 16KB each)
    #define ISSUE(c, st) do { \
        uint32_t so = sb + (uint32_t)(st) * GSTAGE; \
        uint32_t off = (uint32_t)tid * 16; \
        size_t ga = (size_t)(c) * 8192; \
        CPASYNC16(so +        off, gAh + ga + off); \
        CPASYNC16(so + 8192 + off, gAl + ga + off); \
        _Pragma("unroll") \
        for (int nh_ = 0; nh_ < 2; nh_++) { \
            size_t gb = (size_t)(nh_*8 + (c)) * 8192; \
            CPASYNC16(so + 16384 + nh_*8192 + off, gBh + gb + off); \
            CPASYNC16(so + 32768 + nh_*8192 + off, gBl + gb + off); \
        } \
        CPCOMMIT(); \
    } while (0)

    ISSUE(0, 0);
    ISSUE(1, 1);
    ISSUE(2, 2);
    for (int c = 0; c < 8; c++) {
        if (c <= 5)      { CPWAIT(2); }
        else if (c == 6) { CPWAIT(1); }
        else             { CPWAIT(0); }
        __syncthreads();                       // single barrier per iteration
        uint32_t base = sb + (uint32_t)(c & 3) * GSTAGE;
        #pragma unroll
        for (int s = 0; s < 2; s++) {
            uint32_t ah[2][4], al[2][4];
            #pragma unroll
            for (int i = 0; i < 2; i++) {
                uint32_t kc = (uint32_t)((((s<<1)|hi2) ^ asw[i]) << 4);
                LDSM4(ah[i][0],ah[i][1],ah[i][2],ah[i][3], base + aoff[i] + kc);
                LDSM4(al[i][0],al[i][1],al[i][2],al[i][3], base + 8192 + aoff[i] + kc);
            }
            #pragma unroll
            for (int jp = 0; jp < 2; jp++) {   // j pair: {2jp, 2jp+1}
                uint32_t bh[2][4], bl[2][4];
                #pragma unroll
                for (int q = 0; q < 2; q++) {
                    int j = jp*2 + q;
                    uint32_t kc = (uint32_t)((((s<<1)|hi2) ^ bsw[j]) << 4);
                    LDSM4(bh[q][0],bh[q][1],bh[q][2],bh[q][3], base + 16384 + boff[j] + kc);
                    LDSM4(bl[q][0],bl[q][1],bl[q][2],bl[q][3], base + 32768 + boff[j] + kc);
                }
                // hi*hi: 8 MMAs into 8 DISTINCT accumulators
                #pragma unroll
                for (int q = 0; q < 2; q++)
                    #pragma unroll
                    for (int i = 0; i < 2; i++) {
                        MMA16816(d[i][4*jp+2*q],   ah[i], bh[q][0], bh[q][2]);
                        MMA16816(d[i][4*jp+2*q+1], ah[i], bh[q][1], bh[q][3]);
                    }
                // hi*lo: same 8 accumulators, reuse distance 8
                #pragma unroll
                for (int q = 0; q < 2; q++)
                    #pragma unroll
                    for (int i = 0; i < 2; i++) {
                        MMA16816(d[i][4*jp+2*q],   ah[i], bl[q][0], bl[q][2]);
                        MMA16816(d[i][4*jp+2*q+1], ah[i], bl[q][1], bl[q][3]);
                    }
                // lo*hi: same 8 accumulators, reuse distance 8
                #pragma unroll
                for (int q = 0; q < 2; q++)
                    #pragma unroll
                    for (int i = 0; i < 2; i++) {
                        MMA16816(d[i][4*jp+2*q],   al[i], bh[q][0], bh[q][2]);
                        MMA16816(d[i][4*jp+2*q+1], al[i], bh[q][1], bh[q][3]);
                    }
            }
        }
        if (c + 3 < 8) ISSUE(c+3, (c+3) & 3);  // writes buf (c-1)&3: all readers passed this iter's barrier
    }

    // epilogue: fp32 store
    int rr = lane >> 2, cp = (lane & 3) * 2;
    #pragma unroll
    for (int i = 0; i < 2; i++) {
        size_t row = (size_t)tile*128 + mwarp + i*16 + rr;
        #pragma unroll
        for (int j = 0; j < 8; j++) {
            int col = nwarp + j*8 + cp;
            float2 v0 = make_float2(d[i][j][0], d[i][j][1]);
            float2 v1 = make_float2(d[i][j][2], d[i][j][3]);
            *(float2*)&H[row*CC + col]     = v0;
            *(float2*)&H[(row+8)*CC + col] = v1;
        }
    }
}

// ---------------- aggregation ----------------
// acc = sum_in-edges norm*h[b,src,:] + dinv^2*h[b,n,:] + bias (+res), relu.
// block = 1 node x 4 batches (metadata shared); write_img -> hi/lo A images.
__global__ __launch_bounds__(256) void k_agg(const float* __restrict__ h, int set,
                                             const float* __restrict__ bias,
                                             const float* __restrict__ residual,
                                             float* __restrict__ out, int write_img) {
    int g    = threadIdx.x >> 6;           // batch sub-group 0..3
    int lane = threadIdx.x & 63;           // channel/4
    int n = blockIdx.x;
    int b = blockIdx.y * 4 + g;

    const int* ptr = g_ptr + set*(NN+1);
    int p0 = __ldg(&ptr[n]), p1 = __ldg(&ptr[n+1]);
    float dn = __ldg(&g_dinv[set*NN + n]);
    size_t bbase = (size_t)b * NN;
    size_t base  = (bbase + n) * CC + lane*4;

    float4 sv = *(const float4*)&h[base];
    float w = dn * dn;
    float4 acc;
    acc.x = w*sv.x; acc.y = w*sv.y; acc.z = w*sv.z; acc.w = w*sv.w;

    int off = set*MAXE;
    int j = p0;
    for (; j + 4 <= p1; j += 4) {
        int   s0 = __ldg(&g_esrc [off + j]);
        int   s1 = __ldg(&g_esrc [off + j + 1]);
        int   s2 = __ldg(&g_esrc [off + j + 2]);
        int   s3 = __ldg(&g_esrc [off + j + 3]);
        float w0 = __ldg(&g_enorm[off + j]);
        float w1 = __ldg(&g_enorm[off + j + 1]);
        float w2 = __ldg(&g_enorm[off + j + 2]);
        float w3 = __ldg(&g_enorm[off + j + 3]);
        float4 v0 = *(const float4*)&h[(bbase + s0)*CC + lane*4];
        float4 v1 = *(const float4*)&h[(bbase + s1)*CC + lane*4];
        float4 v2 = *(const float4*)&h[(bbase + s2)*CC + lane*4];
        float4 v3 = *(const float4*)&h[(bbase + s3)*CC + lane*4];
        acc.x += w0*v0.x + w1*v1.x + w2*v2.x + w3*v3.x;
        acc.y += w0*v0.y + w1*v1.y + w2*v2.y + w3*v3.y;
        acc.z += w0*v0.z + w1*v1.z + w2*v2.z + w3*v3.z;
        acc.w += w0*v0.w + w1*v1.w + w2*v2.w + w3*v3.w;
    }
    for (; j < p1; ++j) {
        int   s0 = __ldg(&g_esrc [off + j]);
        float w0 = __ldg(&g_enorm[off + j]);
        float4 v0 = *(const float4*)&h[(bbase + s0)*CC + lane*4];
        acc.x += w0*v0.x; acc.y += w0*v0.y; acc.z += w0*v0.z; acc.w += w0*v0.w;
    }

    float4 bi = *(const float4*)&bias[lane*4];
    acc.x += bi.x; acc.y += bi.y; acc.z += bi.z; acc.w += bi.w;
    if (residual) {
        float4 rv = *(const float4*)&residual[base];
        acc.x += rv.x; acc.y += rv.y; acc.z += rv.z; acc.w += rv.w;
    }
    acc.x = fmaxf(acc.x, 0.f); acc.y = fmaxf(acc.y, 0.f);
    acc.z = fmaxf(acc.z, 0.f); acc.w = fmaxf(acc.w, 0.f);

    if (write_img) {
        uint2 hi, lo; split4(acc, hi, lo);
        int m = (int)(bbase + n);
        int tile = m >> 7, mi = m & 127, k = lane*4, chunk = k >> 5, kin = k & 31;
        size_t eo = (size_t)(tile*8 + chunk)*4096 + swz_elem(mi, kin);
        *(uint2*)(g_ah + eo) = hi;
        *(uint2*)(g_al + eo) = lo;
    } else {
        *(float4*)&out[base] = acc;
    }
}

// ---------------- launch ----------------
extern "C" void kernel_launch(void* const* d_in, const int* in_sizes, int n_in,
                              void* d_out, int out_size) {
    const float* x  = (const float*)d_in[0];
    const float* W1 = (const float*)d_in[1];
    const float* b1 = (const float*)d_in[2];
    const float* W2 = (const float*)d_in[3];
    const float* b2 = (const float*)d_in[4];
    const float* W3 = (const float*)d_in[5];
    const float* b3 = (const float*)d_in[6];
    const int*   sp = (const int*)d_in[7];
    const int*   tm = (const int*)d_in[8];
    int Esp = in_sizes[7] / 2;
    int Etm = in_sizes[8] / 2;
    float* out = (float*)d_out;

    float* h; __nv_bfloat16 *bh, *bl;
    cudaGetSymbolAddress((void**)&h,  g_h);
    cudaGetSymbolAddress((void**)&bh, g_bh);
    cudaGetSymbolAddress((void**)&bl, g_bl);

    cudaFuncSetAttribute(k_gemm_mma, cudaFuncAttributeMaxDynamicSharedMemorySize, GSM);

    dim3 ga(NN, BB/4);                // (1700, 16)

    // conversions; GEMM1 early so the ncu sample slot lands on it
    k_convA<<<(MTOT*64 + 255)/256, 256>>>(x);
    k_convW<<<64, 256>>>(W1, 0);
    k_gemm_mma<<<MTILES, 512, GSM>>>(bh, bl, h);
    k_convW<<<64, 256>>>(W2, 1);
    k_convW<<<64, 256>>>(W3, 2);

    // graph prep
    k_init <<<(2*NN + 255)/256, 256>>>();
    k_count<<<(Esp + 255)/256, 256>>>(sp + Esp, Esp, 0);
    k_count<<<(Etm + 255)/256, 256>>>(tm + Etm, Etm, 1);
    k_scan <<<1, 1024>>>(0);
    k_scan <<<1, 1024>>>(1);
    k_fill <<<(Esp + 255)/256, 256>>>(sp, sp + Esp, Esp, 0);
    k_fill <<<(Etm + 255)/256, 256>>>(tm, tm + Etm, Etm, 1);

    // conv1: relu(agg_sp(x@W1)+b1) -> images
    k_agg<<<ga, 256>>>(h, 0, b1, nullptr, nullptr, 1);
    // conv2: relu(agg_tm(.@W2)+b2) -> images
    k_gemm_mma<<<MTILES, 512, GSM>>>(bh + 65536, bl + 65536, h);
    k_agg<<<ga, 256>>>(h, 1, b2, nullptr, nullptr, 1);
    // conv3: relu(agg_sp(.@W3)+b3+x) -> out
    k_gemm_mma<<<MTILES, 512, GSM>>>(bh + 2*65536, bl + 2*65536, h);
    k_agg<<<ga, 256>>>(h, 0, b3, x, out, 0);
}